// round 9
// baseline (speedup 1.0000x reference)
#include <cuda_runtime.h>
#include <cuda_fp16.h>
#include <cstdint>

#define NN 100000
#define NN_PAD 100096          // 782 * 128
#define NE 1600000
#define SCAN_NB 98             // ceil(NN/1024)

// ---------------- scratch (static __device__ arrays; no allocation) ----------
__device__ __half g_yh[NN_PAD * 256]; // [N,256] fp16: [spmm(x*ns)*nd | spmm(x)]
__device__ uint2  g_f0[NN * 32];      // [N,128] fp16 features buffer A
__device__ uint2  g_f1[NN * 32];      // [N,128] fp16 features buffer B
__device__ int    g_csr[NE];          // src ids grouped by dst
__device__ int    g_rank[NE];         // per-edge rank within its dst bucket
__device__ int    g_outdeg[NN];
__device__ int    g_indeg[NN];
__device__ float  g_ns[NN];
__device__ float  g_nd[NN];
__device__ int    g_rowstart[NN + 1];
__device__ int    g_blocksums[128];
__device__ __half g_wt0[128 * 256];   // [128n][256k] fp16: transposed [w0;rw0]
__device__ __half g_wt1[128 * 256];   // [128n][256k] fp16: transposed [w1;rw1]
__device__ __half g_wt2[64 * 256];    // [64n][256k]  fp16: transposed [w2;rw2]

// ---------------- helpers ----------------------------------------------------
__device__ __forceinline__ void mma_f16(float* c, const uint32_t* a, const uint32_t* b) {
    asm volatile(
        "mma.sync.aligned.m16n8k16.row.col.f32.f16.f16.f32 "
        "{%0,%1,%2,%3}, {%4,%5,%6,%7}, {%8,%9}, {%0,%1,%2,%3};\n"
        : "+f"(c[0]), "+f"(c[1]), "+f"(c[2]), "+f"(c[3])
        : "r"(a[0]), "r"(a[1]), "r"(a[2]), "r"(a[3]), "r"(b[0]), "r"(b[1]));
}

__device__ __forceinline__ void cp16(uint32_t dst, const void* src) {
    asm volatile("cp.async.cg.shared.global [%0], [%1], 16;\n" :: "r"(dst), "l"(src));
}
__device__ __forceinline__ void cpcommit() {
    asm volatile("cp.async.commit_group;\n");
}
template <int N>
__device__ __forceinline__ void cpwait() {
    asm volatile("cp.async.wait_group %0;\n" :: "n"(N));
}

// ---------------- fused prep: weights->fp16 transposed, zero degs, x->fp16 ----
__global__ void k_prep(const float4* __restrict__ raw_x,
                       const float* __restrict__ w0, const float* __restrict__ rw0,
                       const float* __restrict__ w1, const float* __restrict__ rw1,
                       const float* __restrict__ w2, const float* __restrict__ rw2) {
    int i = blockIdx.x * blockDim.x + threadIdx.x;
    if (i < 32768) {
        int k = i >> 7, n = i & 127;
        float v = (k < 128) ? w0[k * 128 + n] : rw0[(k - 128) * 128 + n];
        g_wt0[n * 256 + k] = __float2half(v);
    } else if (i < 65536) {
        int j = i - 32768;
        int k = j >> 7, n = j & 127;
        float v = (k < 128) ? w1[k * 128 + n] : rw1[(k - 128) * 128 + n];
        g_wt1[n * 256 + k] = __float2half(v);
    } else if (i < 81920) {
        int j = i - 65536;
        int k = j >> 6, n = j & 63;
        float v = (k < 128) ? w2[k * 64 + n] : rw2[(k - 128) * 64 + n];
        g_wt2[n * 256 + k] = __float2half(v);
    } else if (i < 106920) {
        ((int4*)g_outdeg)[i - 81920] = make_int4(0, 0, 0, 0);
    } else if (i < 131920) {
        ((int4*)g_indeg)[i - 106920] = make_int4(0, 0, 0, 0);
    } else if (i < 3331920) {
        int j = i - 131920;                 // float4 index == uint2 index
        float4 v = raw_x[j];
        __half2 h0 = __floats2half2_rn(v.x, v.y);
        __half2 h1 = __floats2half2_rn(v.z, v.w);
        uint2 u;
        u.x = *reinterpret_cast<uint32_t*>(&h0);
        u.y = *reinterpret_cast<uint32_t*>(&h1);
        g_f0[j] = u;
    }
}

// ---------------- degree count + per-edge dst rank ----------------------------
__global__ void k_deg(const int4* __restrict__ src4, const int4* __restrict__ dst4) {
    int e = blockIdx.x * blockDim.x + threadIdx.x;
    if (e < NE / 4) {
        int4 s = src4[e];
        int4 d = dst4[e];
        atomicAdd(&g_outdeg[s.x], 1); atomicAdd(&g_outdeg[s.y], 1);
        atomicAdd(&g_outdeg[s.z], 1); atomicAdd(&g_outdeg[s.w], 1);
        int4 r;
        r.x = atomicAdd(&g_indeg[d.x], 1);
        r.y = atomicAdd(&g_indeg[d.y], 1);
        r.z = atomicAdd(&g_indeg[d.z], 1);
        r.w = atomicAdd(&g_indeg[d.w], 1);
        ((int4*)g_rank)[e] = r;
    }
}

// exclusive scan of g_indeg: per-block scan + blocksums
__global__ void k_scan1() {
    __shared__ int sh[1024];
    int t = threadIdx.x;
    int i = blockIdx.x * 1024 + t;
    int v = (i < NN) ? g_indeg[i] : 0;
    sh[t] = v;
    __syncthreads();
    #pragma unroll
    for (int off = 1; off < 1024; off <<= 1) {
        int add = (t >= off) ? sh[t - off] : 0;
        __syncthreads();
        sh[t] += add;
        __syncthreads();
    }
    if (i < NN) g_rowstart[i] = sh[t] - v;  // exclusive within block
    if (t == 1023) g_blocksums[blockIdx.x] = sh[1023];
}

// apply block offsets + compute norms (Hillis-Steele over blocksums)
__global__ void k_scan23() {
    __shared__ int sh[128];
    int t = threadIdx.x;
    int v = (t < SCAN_NB) ? g_blocksums[t] : 0;
    if (t < 128) sh[t] = v;
    __syncthreads();
    #pragma unroll
    for (int off = 1; off < 128; off <<= 1) {
        int add = (t < 128 && t >= off) ? sh[t - off] : 0;
        __syncthreads();
        if (t < 128) sh[t] += add;
        __syncthreads();
    }
    int i = blockIdx.x * blockDim.x + t;
    if (i < NN) {
        int b = i >> 10;
        int pre = (b > 0) ? sh[b - 1] : 0;
        g_rowstart[i] += pre;
        g_ns[i] = rsqrtf(fmaxf((float)g_outdeg[i], 1.0f));
        g_nd[i] = rsqrtf(fmaxf((float)g_indeg[i], 1.0f));
    }
    if (i == 0) g_rowstart[NN] = NE;
}

// atomic-free CSR fill: pos = rowstart[dst] + rank
__global__ void k_csr(const int4* __restrict__ src4, const int4* __restrict__ dst4) {
    int e = blockIdx.x * blockDim.x + threadIdx.x;
    if (e < NE / 4) {
        int4 s = src4[e];
        int4 d = dst4[e];
        int4 r = ((const int4*)g_rank)[e];
        g_csr[g_rowstart[d.x] + r.x] = s.x;
        g_csr[g_rowstart[d.y] + r.y] = s.y;
        g_csr[g_rowstart[d.z] + r.z] = s.z;
        g_csr[g_rowstart[d.w] + r.w] = s.w;
    }
}

// ---------------- SpMM via tensor cores --------------------------------------
// One warp per node. Per 16-edge chunk:
//   A (m16k16, fp16): row 0 = ns_j coefficients, row 8 = validity ones, rest 0
//   B (k16n8 via ldmatrix.trans): gathered fp16 feature rows (cp.async staging)
//   D (fp32): lanes grp==0 hold weighted sum in c0/c1 and raw sum in c2/c3.
#define STG_ROW 272                       // staging row stride (bytes), LDSM-friendly
#define STG_BYTES (16 * STG_ROW)          // 4352 B per warp

__global__ __launch_bounds__(256) void k_spmm(const char* __restrict__ xbytes) {
    __shared__ __align__(16) char stage[8][STG_BYTES];   // 34816 B
    const int warp = threadIdx.x >> 5, lane = threadIdx.x & 31;
    const int grp = lane >> 2, tig = lane & 3;
    char* buf = stage[warp];
    const uint32_t bufaddr = (uint32_t)__cvta_generic_to_shared(buf);

    // zero staging once (invalid rows multiply by 0 coeff; avoid stale NaNs)
    #pragma unroll
    for (int i = 0; i < 9; ++i) {
        int off = i * 512 + lane * 16;
        if (off < STG_BYTES) *reinterpret_cast<uint4*>(buf + off) = make_uint4(0, 0, 0, 0);
    }
    __syncwarp();

    const int w = (blockIdx.x * 256 + threadIdx.x) >> 5;
    if (w >= NN) return;
    const int s = g_rowstart[w], e = g_rowstart[w + 1];

    float acc[16][4];
    #pragma unroll
    for (int T = 0; T < 16; ++T) {
        acc[T][0] = 0.f; acc[T][1] = 0.f; acc[T][2] = 0.f; acc[T][3] = 0.f;
    }

    for (int p = s; p < e; p += 16) {
        const int k = p + lane;
        const bool valid = (lane < 16) && (k < e);
        int j = 0;
        float nsf = 0.f, onef = 0.f;
        if (valid) {
            j = g_csr[k];
            nsf = g_ns[j];
            onef = 1.f;
        }
        // Build A fragments (only grp==0 lanes carry data: rows 0 and 8)
        uint32_t a0 = 0, a1 = 0, a2 = 0, a3 = 0;
        {
            float n0 = __shfl_sync(0xFFFFFFFFu, nsf, 2 * tig);
            float n1 = __shfl_sync(0xFFFFFFFFu, nsf, 2 * tig + 1);
            float n2 = __shfl_sync(0xFFFFFFFFu, nsf, 2 * tig + 8);
            float n3 = __shfl_sync(0xFFFFFFFFu, nsf, 2 * tig + 9);
            float o0 = __shfl_sync(0xFFFFFFFFu, onef, 2 * tig);
            float o1 = __shfl_sync(0xFFFFFFFFu, onef, 2 * tig + 1);
            float o2 = __shfl_sync(0xFFFFFFFFu, onef, 2 * tig + 8);
            float o3 = __shfl_sync(0xFFFFFFFFu, onef, 2 * tig + 9);
            if (grp == 0) {
                __half2 h;
                h = __floats2half2_rn(n0, n1); a0 = *reinterpret_cast<uint32_t*>(&h);
                h = __floats2half2_rn(o0, o1); a1 = *reinterpret_cast<uint32_t*>(&h);
                h = __floats2half2_rn(n2, n3); a2 = *reinterpret_cast<uint32_t*>(&h);
                h = __floats2half2_rn(o2, o3); a3 = *reinterpret_cast<uint32_t*>(&h);
            }
        }
        // Gather 16 feature rows (256B each) into staging via cp.async
        #pragma unroll
        for (int i2 = 0; i2 < 8; ++i2) {
            int row = 2 * i2 + (lane >> 4);
            int jr = __shfl_sync(0xFFFFFFFFu, j, row);
            int vr = __shfl_sync(0xFFFFFFFFu, (int)valid, row);
            if (vr)
                cp16(bufaddr + row * STG_ROW + (lane & 15) * 16,
                     xbytes + (size_t)jr * 256 + (lane & 15) * 16);
        }
        cpcommit();
        cpwait<0>();
        __syncwarp();
        // 8x ldmatrix.x4.trans (k16 x n16 each) + 16 mma
        #pragma unroll
        for (int t = 0; t < 8; ++t) {
            uint32_t d0, d1, d2, d3;
            uint32_t addr = bufaddr + (lane & 15) * STG_ROW + (lane >> 4) * 16 + t * 32;
            asm volatile(
                "ldmatrix.sync.aligned.m8n8.x4.trans.shared.b16 {%0,%1,%2,%3}, [%4];"
                : "=r"(d0), "=r"(d1), "=r"(d2), "=r"(d3) : "r"(addr));
            uint32_t A[4] = {a0, a1, a2, a3};
            uint32_t B0[2] = {d0, d1};
            uint32_t B1[2] = {d2, d3};
            mma_f16(acc[2 * t], A, B0);
            mma_f16(acc[2 * t + 1], A, B1);
        }
    }

    // Epilogue: lanes grp==0 hold row0 (weighted) in c0/c1, row8 (raw) in c2/c3
    float nd = g_nd[w];
    if (grp == 0) {
        __half* yrow = g_yh + (size_t)w * 256;
        #pragma unroll
        for (int T = 0; T < 16; ++T) {
            __half2 hw = __floats2half2_rn(acc[T][0] * nd, acc[T][1] * nd);
            __half2 hr = __floats2half2_rn(acc[T][2], acc[T][3]);
            *reinterpret_cast<__half2*>(yrow + T * 8 + 2 * tig) = hw;
            *reinterpret_cast<__half2*>(yrow + 128 + T * 8 + 2 * tig) = hr;
        }
    }
}

// ---------------- GEMM: C[M,BN] = A[M,256] @ Bt[BN,256]^T + bias (fp16 mma) ---
template <int BN, bool RELU, bool HALFOUT>
__global__ __launch_bounds__(256) void k_gemm(
    const uint32_t* __restrict__ A, const uint32_t* __restrict__ Bw,
    const float* __restrict__ bias, void* __restrict__ Cv)
{
    constexpr int BM = 128;
    constexpr int AS = 36;                 // stage row stride in words (64h + pad)
    constexpr int ASTG = BM * AS;
    constexpr int BSTG = BN * AS;
    constexpr int NT = BN / 16;            // n-tiles per warp (warp n-span BN/2)
    constexpr int NKC = 4;                 // 256 / 64 chunks

    extern __shared__ uint32_t dyn[];
    uint32_t* sA = dyn;
    uint32_t* sB = dyn + 2 * ASTG;
    const uint32_t saddrA = (uint32_t)__cvta_generic_to_shared(sA);
    const uint32_t saddrB = (uint32_t)__cvta_generic_to_shared(sB);

    const int tid  = threadIdx.x;
    const int warp = tid >> 5, lane = tid & 31;
    const int grp  = lane >> 2, tig = lane & 3;
    const int wm   = (warp >> 1) * 32;
    const int wn   = (warp & 1) * (BN / 2);
    const int blockRow = blockIdx.x * BM;

    auto stage = [&](int kc, int buf) {
        #pragma unroll
        for (int it = 0; it < 4; ++it) {       // A chunk: 128 rows x 64 halves
            int idx = tid + it * 256;
            int r = idx >> 3, c = idx & 7;
            cp16(saddrA + (uint32_t)(buf * ASTG + r * AS + c * 4) * 4,
                 A + (size_t)(blockRow + r) * 128 + kc * 32 + c * 4);
        }
        #pragma unroll
        for (int it = 0; it < BN / 32; ++it) { // B chunk: BN rows x 64 halves
            int idx = tid + it * 256;
            int r = idx >> 3, c = idx & 7;
            cp16(saddrB + (uint32_t)(buf * BSTG + r * AS + c * 4) * 4,
                 Bw + (size_t)r * 128 + kc * 32 + c * 4);
        }
        cpcommit();
    };

    float acc[2][NT][4];
    #pragma unroll
    for (int mt = 0; mt < 2; mt++)
        #pragma unroll
        for (int nt = 0; nt < NT; nt++)
            #pragma unroll
            for (int r = 0; r < 4; r++) acc[mt][nt][r] = 0.f;

    stage(0, 0);
    #pragma unroll
    for (int kc = 0; kc < NKC; ++kc) {
        int buf = kc & 1;
        if (kc + 1 < NKC) {
            stage(kc + 1, buf ^ 1);
            cpwait<1>();
        } else {
            cpwait<0>();
        }
        __syncthreads();

        const uint32_t* cA = sA + buf * ASTG;
        const uint32_t* cB = sB + buf * BSTG;
        #pragma unroll
        for (int ks = 0; ks < 4; ++ks) {       // 4 x k16 per 64-half chunk
            uint32_t af[2][4];
            #pragma unroll
            for (int mt = 0; mt < 2; mt++) {
                int row = wm + mt * 16 + grp;
                int ko = ks * 8 + tig;
                af[mt][0] = cA[row * AS + ko];
                af[mt][1] = cA[(row + 8) * AS + ko];
                af[mt][2] = cA[row * AS + ko + 4];
                af[mt][3] = cA[(row + 8) * AS + ko + 4];
            }
            uint32_t bf[NT][2];
            #pragma unroll
            for (int nt = 0; nt < NT; nt++) {
                int col = wn + nt * 8 + grp;
                int ko = ks * 8 + tig;
                bf[nt][0] = cB[col * AS + ko];
                bf[nt][1] = cB[col * AS + ko + 4];
            }
            #pragma unroll
            for (int mt = 0; mt < 2; mt++)
                #pragma unroll
                for (int nt = 0; nt < NT; nt++)
                    mma_f16(acc[mt][nt], af[mt], bf[nt]);
        }
        __syncthreads();
    }

    // epilogue: bias (+relu), half2 or float2 stores
    #pragma unroll
    for (int mt = 0; mt < 2; ++mt) {
        int r0 = blockRow + wm + mt * 16 + grp;
        int r1 = r0 + 8;
        #pragma unroll
        for (int nt = 0; nt < NT; ++nt) {
            int col = wn + nt * 8 + 2 * tig;
            float b0v = bias[col], b1v = bias[col + 1];
            float v0 = acc[mt][nt][0] + b0v;
            float v1 = acc[mt][nt][1] + b1v;
            float v2 = acc[mt][nt][2] + b0v;
            float v3 = acc[mt][nt][3] + b1v;
            if (RELU) {
                v0 = fmaxf(v0, 0.f); v1 = fmaxf(v1, 0.f);
                v2 = fmaxf(v2, 0.f); v3 = fmaxf(v3, 0.f);
            }
            if (HALFOUT) {
                __half* C = (__half*)Cv;
                if (r0 < NN)
                    *reinterpret_cast<__half2*>(&C[(size_t)r0 * BN + col]) =
                        __floats2half2_rn(v0, v1);
                if (r1 < NN)
                    *reinterpret_cast<__half2*>(&C[(size_t)r1 * BN + col]) =
                        __floats2half2_rn(v2, v3);
            } else {
                float* C = (float*)Cv;
                if (r0 < NN)
                    *reinterpret_cast<float2*>(&C[(size_t)r0 * BN + col]) = make_float2(v0, v1);
                if (r1 < NN)
                    *reinterpret_cast<float2*>(&C[(size_t)r1 * BN + col]) = make_float2(v2, v3);
            }
        }
    }
}

// ---------------- launcher ----------------------------------------------------
extern "C" void kernel_launch(void* const* d_in, const int* in_sizes, int n_in,
                              void* d_out, int out_size) {
    const float* raw_x = (const float*)d_in[0];
    const int*   src   = (const int*)d_in[1];
    const int*   dst   = (const int*)d_in[2];
    const float* w0    = (const float*)d_in[3];
    const float* b0    = (const float*)d_in[4];
    const float* w1    = (const float*)d_in[5];
    const float* b1    = (const float*)d_in[6];
    const float* w2    = (const float*)d_in[7];
    const float* b2    = (const float*)d_in[8];
    const float* rw0   = (const float*)d_in[9];
    const float* rw1   = (const float*)d_in[10];
    const float* rw2   = (const float*)d_in[11];
    float* out = (float*)d_out;

    void *py = nullptr, *pf0 = nullptr, *pf1 = nullptr;
    void *pw0 = nullptr, *pw1 = nullptr, *pw2 = nullptr;
    cudaGetSymbolAddress(&py, g_yh);
    cudaGetSymbolAddress(&pf0, g_f0);
    cudaGetSymbolAddress(&pf1, g_f1);
    cudaGetSymbolAddress(&pw0, g_wt0);
    cudaGetSymbolAddress(&pw1, g_wt1);
    cudaGetSymbolAddress(&pw2, g_wt2);

    constexpr int SMEM128 = 2 * (128 * 36 + 128 * 36) * 4;  // 73728
    constexpr int SMEM64  = 2 * (128 * 36 + 64 * 36) * 4;   // 55296
    cudaFuncSetAttribute(k_gemm<128, true, true>,
                         cudaFuncAttributeMaxDynamicSharedMemorySize, SMEM128);
    cudaFuncSetAttribute(k_gemm<64, false, false>,
                         cudaFuncAttributeMaxDynamicSharedMemorySize, SMEM64);

    const int TB = 256;
    k_prep<<<(3331920 + TB - 1) / TB, TB>>>((const float4*)raw_x,
                                            w0, rw0, w1, rw1, w2, rw2);
    k_deg<<<(NE / 4 + TB - 1) / TB, TB>>>((const int4*)src, (const int4*)dst);
    k_scan1<<<SCAN_NB, 1024>>>();
    k_scan23<<<(NN + TB - 1) / TB, TB>>>();
    k_csr<<<(NE / 4 + TB - 1) / TB, TB>>>((const int4*)src, (const int4*)dst);

    const int SPMM_BLOCKS = (NN * 32 + TB - 1) / TB;  // one warp per node
    const int GEMM_BLOCKS = NN_PAD / 128;             // 782

    // layer 1: spmm(g_f0=x) -> g_yh ; gemm -> g_f1 (h1, fp16)
    k_spmm<<<SPMM_BLOCKS, TB>>>((const char*)pf0);
    k_gemm<128, true, true><<<GEMM_BLOCKS, TB, SMEM128>>>(
        (const uint32_t*)py, (const uint32_t*)pw0, b0, pf1);
    // layer 2: spmm(g_f1) -> g_yh ; gemm -> g_f0 (h2, fp16)
    k_spmm<<<SPMM_BLOCKS, TB>>>((const char*)pf1);
    k_gemm<128, true, true><<<GEMM_BLOCKS, TB, SMEM128>>>(
        (const uint32_t*)py, (const uint32_t*)pw1, b1, pf0);
    // layer 3: spmm(g_f0) -> g_yh ; gemm -> d_out (fp32)
    k_spmm<<<SPMM_BLOCKS, TB>>>((const char*)pf0);
    k_gemm<64, false, false><<<GEMM_BLOCKS, TB, SMEM64>>>(
        (const uint32_t*)py, (const uint32_t*)pw2, b2, out);
}

// round 10
// speedup vs baseline: 1.6326x; 1.6326x over previous
#include <cuda_runtime.h>
#include <cuda_fp16.h>
#include <cstdint>

#define NN 100000
#define NN_PAD 100096          // 782 * 128
#define NE 1600000
#define SCAN_NB 98             // ceil(NN/1024)

// ---------------- scratch (static __device__ arrays; no allocation) ----------
__device__ __half g_yh[NN_PAD * 256]; // [N,256] fp16: [spmm(x*ns)*nd | spmm(x)]
__device__ uint2  g_f0[NN * 32];      // [N,128] fp16 features buffer A
__device__ uint2  g_f1[NN * 32];      // [N,128] fp16 features buffer B
__device__ int    g_csr[NE];          // src ids grouped by dst
__device__ int    g_rank[NE];         // per-edge rank within its dst bucket
__device__ int    g_outdeg[NN];
__device__ int    g_indeg[NN];
__device__ float  g_ns[NN];
__device__ float  g_nd[NN];
__device__ int    g_rowstart[NN + 1];
__device__ int    g_blocksums[128];
__device__ __half g_wt0[128 * 256];   // [128n][256k] fp16: transposed [w0;rw0]
__device__ __half g_wt1[128 * 256];   // [128n][256k] fp16: transposed [w1;rw1]
__device__ __half g_wt2[64 * 256];    // [64n][256k]  fp16: transposed [w2;rw2]

// ---------------- helpers ----------------------------------------------------
__device__ __forceinline__ void mma_f16(float* c, const uint32_t* a, const uint32_t* b) {
    asm volatile(
        "mma.sync.aligned.m16n8k16.row.col.f32.f16.f16.f32 "
        "{%0,%1,%2,%3}, {%4,%5,%6,%7}, {%8,%9}, {%0,%1,%2,%3};\n"
        : "+f"(c[0]), "+f"(c[1]), "+f"(c[2]), "+f"(c[3])
        : "r"(a[0]), "r"(a[1]), "r"(a[2]), "r"(a[3]), "r"(b[0]), "r"(b[1]));
}

__device__ __forceinline__ void cp16(uint32_t dst, const void* src) {
    asm volatile("cp.async.cg.shared.global [%0], [%1], 16;\n" :: "r"(dst), "l"(src));
}
__device__ __forceinline__ void cpcommit() {
    asm volatile("cp.async.commit_group;\n");
}
template <int N>
__device__ __forceinline__ void cpwait() {
    asm volatile("cp.async.wait_group %0;\n" :: "n"(N));
}

// ---------------- fused prep: weights->fp16 transposed, zero degs, x->fp16 ----
__global__ void k_prep(const float4* __restrict__ raw_x,
                       const float* __restrict__ w0, const float* __restrict__ rw0,
                       const float* __restrict__ w1, const float* __restrict__ rw1,
                       const float* __restrict__ w2, const float* __restrict__ rw2) {
    int i = blockIdx.x * blockDim.x + threadIdx.x;
    if (i < 32768) {
        int k = i >> 7, n = i & 127;
        float v = (k < 128) ? w0[k * 128 + n] : rw0[(k - 128) * 128 + n];
        g_wt0[n * 256 + k] = __float2half(v);
    } else if (i < 65536) {
        int j = i - 32768;
        int k = j >> 7, n = j & 127;
        float v = (k < 128) ? w1[k * 128 + n] : rw1[(k - 128) * 128 + n];
        g_wt1[n * 256 + k] = __float2half(v);
    } else if (i < 81920) {
        int j = i - 65536;
        int k = j >> 6, n = j & 63;
        float v = (k < 128) ? w2[k * 64 + n] : rw2[(k - 128) * 64 + n];
        g_wt2[n * 256 + k] = __float2half(v);
    } else if (i < 106920) {
        ((int4*)g_outdeg)[i - 81920] = make_int4(0, 0, 0, 0);
    } else if (i < 131920) {
        ((int4*)g_indeg)[i - 106920] = make_int4(0, 0, 0, 0);
    } else if (i < 3331920) {
        int j = i - 131920;                 // float4 index == uint2 index
        float4 v = raw_x[j];
        __half2 h0 = __floats2half2_rn(v.x, v.y);
        __half2 h1 = __floats2half2_rn(v.z, v.w);
        uint2 u;
        u.x = *reinterpret_cast<uint32_t*>(&h0);
        u.y = *reinterpret_cast<uint32_t*>(&h1);
        g_f0[j] = u;
    }
}

// ---------------- degree count + per-edge dst rank ----------------------------
__global__ void k_deg(const int4* __restrict__ src4, const int4* __restrict__ dst4) {
    int e = blockIdx.x * blockDim.x + threadIdx.x;
    if (e < NE / 4) {
        int4 s = src4[e];
        int4 d = dst4[e];
        atomicAdd(&g_outdeg[s.x], 1); atomicAdd(&g_outdeg[s.y], 1);
        atomicAdd(&g_outdeg[s.z], 1); atomicAdd(&g_outdeg[s.w], 1);
        int4 r;
        r.x = atomicAdd(&g_indeg[d.x], 1);
        r.y = atomicAdd(&g_indeg[d.y], 1);
        r.z = atomicAdd(&g_indeg[d.z], 1);
        r.w = atomicAdd(&g_indeg[d.w], 1);
        ((int4*)g_rank)[e] = r;
    }
}

// exclusive scan of g_indeg (per-block) + blocksums + norms
__global__ void k_scan1() {
    __shared__ int sh[1024];
    int t = threadIdx.x;
    int i = blockIdx.x * 1024 + t;
    int v = (i < NN) ? g_indeg[i] : 0;
    sh[t] = v;
    __syncthreads();
    #pragma unroll
    for (int off = 1; off < 1024; off <<= 1) {
        int add = (t >= off) ? sh[t - off] : 0;
        __syncthreads();
        sh[t] += add;
        __syncthreads();
    }
    if (i < NN) {
        g_rowstart[i] = sh[t] - v;  // exclusive within block
        g_ns[i] = rsqrtf(fmaxf((float)g_outdeg[i], 1.0f));
        g_nd[i] = rsqrtf(fmaxf((float)v, 1.0f));
    }
    if (t == 1023) g_blocksums[blockIdx.x] = sh[1023];
}

// apply block offsets (Hillis-Steele over blocksums)
__global__ void k_scan23() {
    __shared__ int sh[128];
    int t = threadIdx.x;
    int v = (t < SCAN_NB) ? g_blocksums[t] : 0;
    if (t < 128) sh[t] = v;
    __syncthreads();
    #pragma unroll
    for (int off = 1; off < 128; off <<= 1) {
        int add = (t < 128 && t >= off) ? sh[t - off] : 0;
        __syncthreads();
        if (t < 128) sh[t] += add;
        __syncthreads();
    }
    int i = blockIdx.x * blockDim.x + t;
    if (i < NN) {
        int b = i >> 10;
        int pre = (b > 0) ? sh[b - 1] : 0;
        g_rowstart[i] += pre;
    }
    if (i == 0) g_rowstart[NN] = NE;
}

// atomic-free CSR fill: pos = rowstart[dst] + rank
__global__ void k_csr(const int4* __restrict__ src4, const int4* __restrict__ dst4) {
    int e = blockIdx.x * blockDim.x + threadIdx.x;
    if (e < NE / 4) {
        int4 s = src4[e];
        int4 d = dst4[e];
        int4 r = ((const int4*)g_rank)[e];
        g_csr[g_rowstart[d.x] + r.x] = s.x;
        g_csr[g_rowstart[d.y] + r.y] = s.y;
        g_csr[g_rowstart[d.z] + r.z] = s.z;
        g_csr[g_rowstart[d.w] + r.w] = s.w;
    }
}

// ---------------- SpMM: warp per node, fp16 gather, dual fp32 accum -----------
// __launch_bounds__(256, 4): allow 64 regs/thread so the unroll-8 load pipeline
// (j[8], n[8], u[8]) stays register-resident -> true MLP 8 per warp.
__device__ __forceinline__ void acc_edge(uint2 u, float n, float* a1, float* a2) {
    float2 f0 = __half22float2(*reinterpret_cast<__half2*>(&u.x));
    float2 f1 = __half22float2(*reinterpret_cast<__half2*>(&u.y));
    a2[0] += f0.x; a2[1] += f0.y; a2[2] += f1.x; a2[3] += f1.y;
    a1[0] = fmaf(f0.x, n, a1[0]); a1[1] = fmaf(f0.y, n, a1[1]);
    a1[2] = fmaf(f1.x, n, a1[2]); a1[3] = fmaf(f1.y, n, a1[3]);
}

__global__ __launch_bounds__(256, 4) void k_spmm(const uint2* __restrict__ x) {
    int w    = (blockIdx.x * 256 + threadIdx.x) >> 5;
    int lane = threadIdx.x & 31;
    if (w >= NN) return;
    int s = g_rowstart[w];
    int e = g_rowstart[w + 1];
    float a1[4] = {0.f, 0.f, 0.f, 0.f};
    float a2[4] = {0.f, 0.f, 0.f, 0.f};
    int p = s;
    for (; p + 7 < e; p += 8) {
        int   j[8];
        float n[8];
        uint2 u[8];
        #pragma unroll
        for (int q = 0; q < 8; ++q) j[q] = g_csr[p + q];
        #pragma unroll
        for (int q = 0; q < 8; ++q) n[q] = g_ns[j[q]];
        #pragma unroll
        for (int q = 0; q < 8; ++q) u[q] = x[(size_t)j[q] * 32 + lane];
        #pragma unroll
        for (int q = 0; q < 8; ++q) acc_edge(u[q], n[q], a1, a2);
    }
    for (; p < e; ++p) {
        int j0 = g_csr[p];
        float n0 = g_ns[j0];
        uint2 u0 = x[(size_t)j0 * 32 + lane];
        acc_edge(u0, n0, a1, a2);
    }
    float nd = g_nd[w];
    __half2 p0 = __floats2half2_rn(a1[0] * nd, a1[1] * nd);
    __half2 p1 = __floats2half2_rn(a1[2] * nd, a1[3] * nd);
    __half2 p2 = __floats2half2_rn(a2[0], a2[1]);
    __half2 p3 = __floats2half2_rn(a2[2], a2[3]);
    uint2 o1, o2;
    o1.x = *reinterpret_cast<uint32_t*>(&p0);
    o1.y = *reinterpret_cast<uint32_t*>(&p1);
    o2.x = *reinterpret_cast<uint32_t*>(&p2);
    o2.y = *reinterpret_cast<uint32_t*>(&p3);
    uint2* yp = (uint2*)g_yh;
    yp[(size_t)w * 64 + lane]      = o1;
    yp[(size_t)w * 64 + 32 + lane] = o2;
}

// ---------------- GEMM: C[M,BN] = A[M,256] @ Bt[BN,256]^T + bias (fp16 mma) ---
template <int BN, bool RELU, bool HALFOUT>
__global__ __launch_bounds__(256) void k_gemm(
    const uint32_t* __restrict__ A, const uint32_t* __restrict__ Bw,
    const float* __restrict__ bias, void* __restrict__ Cv)
{
    constexpr int BM = 128;
    constexpr int AS = 36;                 // stage row stride in words (64h + pad)
    constexpr int ASTG = BM * AS;
    constexpr int BSTG = BN * AS;
    constexpr int NT = BN / 16;            // n-tiles per warp (warp n-span BN/2)
    constexpr int NKC = 4;                 // 256 / 64 chunks

    extern __shared__ uint32_t dyn[];
    uint32_t* sA = dyn;
    uint32_t* sB = dyn + 2 * ASTG;
    const uint32_t saddrA = (uint32_t)__cvta_generic_to_shared(sA);
    const uint32_t saddrB = (uint32_t)__cvta_generic_to_shared(sB);

    const int tid  = threadIdx.x;
    const int warp = tid >> 5, lane = tid & 31;
    const int grp  = lane >> 2, tig = lane & 3;
    const int wm   = (warp >> 1) * 32;
    const int wn   = (warp & 1) * (BN / 2);
    const int blockRow = blockIdx.x * BM;

    auto stage = [&](int kc, int buf) {
        #pragma unroll
        for (int it = 0; it < 4; ++it) {       // A chunk: 128 rows x 64 halves
            int idx = tid + it * 256;
            int r = idx >> 3, c = idx & 7;
            cp16(saddrA + (uint32_t)(buf * ASTG + r * AS + c * 4) * 4,
                 A + (size_t)(blockRow + r) * 128 + kc * 32 + c * 4);
        }
        #pragma unroll
        for (int it = 0; it < BN / 32; ++it) { // B chunk: BN rows x 64 halves
            int idx = tid + it * 256;
            int r = idx >> 3, c = idx & 7;
            cp16(saddrB + (uint32_t)(buf * BSTG + r * AS + c * 4) * 4,
                 Bw + (size_t)r * 128 + kc * 32 + c * 4);
        }
        cpcommit();
    };

    float acc[2][NT][4];
    #pragma unroll
    for (int mt = 0; mt < 2; mt++)
        #pragma unroll
        for (int nt = 0; nt < NT; nt++)
            #pragma unroll
            for (int r = 0; r < 4; r++) acc[mt][nt][r] = 0.f;

    stage(0, 0);
    #pragma unroll
    for (int kc = 0; kc < NKC; ++kc) {
        int buf = kc & 1;
        if (kc + 1 < NKC) {
            stage(kc + 1, buf ^ 1);
            cpwait<1>();
        } else {
            cpwait<0>();
        }
        __syncthreads();

        const uint32_t* cA = sA + buf * ASTG;
        const uint32_t* cB = sB + buf * BSTG;
        #pragma unroll
        for (int ks = 0; ks < 4; ++ks) {       // 4 x k16 per 64-half chunk
            uint32_t af[2][4];
            #pragma unroll
            for (int mt = 0; mt < 2; mt++) {
                int row = wm + mt * 16 + grp;
                int ko = ks * 8 + tig;
                af[mt][0] = cA[row * AS + ko];
                af[mt][1] = cA[(row + 8) * AS + ko];
                af[mt][2] = cA[row * AS + ko + 4];
                af[mt][3] = cA[(row + 8) * AS + ko + 4];
            }
            uint32_t bf[NT][2];
            #pragma unroll
            for (int nt = 0; nt < NT; nt++) {
                int col = wn + nt * 8 + grp;
                int ko = ks * 8 + tig;
                bf[nt][0] = cB[col * AS + ko];
                bf[nt][1] = cB[col * AS + ko + 4];
            }
            #pragma unroll
            for (int mt = 0; mt < 2; mt++)
                #pragma unroll
                for (int nt = 0; nt < NT; nt++)
                    mma_f16(acc[mt][nt], af[mt], bf[nt]);
        }
        __syncthreads();
    }

    // epilogue: bias (+relu), half2 or float2 stores
    #pragma unroll
    for (int mt = 0; mt < 2; ++mt) {
        int r0 = blockRow + wm + mt * 16 + grp;
        int r1 = r0 + 8;
        #pragma unroll
        for (int nt = 0; nt < NT; ++nt) {
            int col = wn + nt * 8 + 2 * tig;
            float b0v = bias[col], b1v = bias[col + 1];
            float v0 = acc[mt][nt][0] + b0v;
            float v1 = acc[mt][nt][1] + b1v;
            float v2 = acc[mt][nt][2] + b0v;
            float v3 = acc[mt][nt][3] + b1v;
            if (RELU) {
                v0 = fmaxf(v0, 0.f); v1 = fmaxf(v1, 0.f);
                v2 = fmaxf(v2, 0.f); v3 = fmaxf(v3, 0.f);
            }
            if (HALFOUT) {
                __half* C = (__half*)Cv;
                if (r0 < NN)
                    *reinterpret_cast<__half2*>(&C[(size_t)r0 * BN + col]) =
                        __floats2half2_rn(v0, v1);
                if (r1 < NN)
                    *reinterpret_cast<__half2*>(&C[(size_t)r1 * BN + col]) =
                        __floats2half2_rn(v2, v3);
            } else {
                float* C = (float*)Cv;
                if (r0 < NN)
                    *reinterpret_cast<float2*>(&C[(size_t)r0 * BN + col]) = make_float2(v0, v1);
                if (r1 < NN)
                    *reinterpret_cast<float2*>(&C[(size_t)r1 * BN + col]) = make_float2(v2, v3);
            }
        }
    }
}

// ---------------- launcher ----------------------------------------------------
extern "C" void kernel_launch(void* const* d_in, const int* in_sizes, int n_in,
                              void* d_out, int out_size) {
    const float* raw_x = (const float*)d_in[0];
    const int*   src   = (const int*)d_in[1];
    const int*   dst   = (const int*)d_in[2];
    const float* w0    = (const float*)d_in[3];
    const float* b0    = (const float*)d_in[4];
    const float* w1    = (const float*)d_in[5];
    const float* b1    = (const float*)d_in[6];
    const float* w2    = (const float*)d_in[7];
    const float* b2    = (const float*)d_in[8];
    const float* rw0   = (const float*)d_in[9];
    const float* rw1   = (const float*)d_in[10];
    const float* rw2   = (const float*)d_in[11];
    float* out = (float*)d_out;

    void *py = nullptr, *pf0 = nullptr, *pf1 = nullptr;
    void *pw0 = nullptr, *pw1 = nullptr, *pw2 = nullptr;
    cudaGetSymbolAddress(&py, g_yh);
    cudaGetSymbolAddress(&pf0, g_f0);
    cudaGetSymbolAddress(&pf1, g_f1);
    cudaGetSymbolAddress(&pw0, g_wt0);
    cudaGetSymbolAddress(&pw1, g_wt1);
    cudaGetSymbolAddress(&pw2, g_wt2);

    constexpr int SMEM128 = 2 * (128 * 36 + 128 * 36) * 4;  // 73728
    constexpr int SMEM64  = 2 * (128 * 36 + 64 * 36) * 4;   // 55296
    cudaFuncSetAttribute(k_gemm<128, true, true>,
                         cudaFuncAttributeMaxDynamicSharedMemorySize, SMEM128);
    cudaFuncSetAttribute(k_gemm<64, false, false>,
                         cudaFuncAttributeMaxDynamicSharedMemorySize, SMEM64);

    const int TB = 256;
    k_prep<<<(3331920 + TB - 1) / TB, TB>>>((const float4*)raw_x,
                                            w0, rw0, w1, rw1, w2, rw2);
    k_deg<<<(NE / 4 + TB - 1) / TB, TB>>>((const int4*)src, (const int4*)dst);
    k_scan1<<<SCAN_NB, 1024>>>();
    k_scan23<<<(NN + TB - 1) / TB, TB>>>();
    k_csr<<<(NE / 4 + TB - 1) / TB, TB>>>((const int4*)src, (const int4*)dst);

    const int SPMM_BLOCKS = (NN * 32 + TB - 1) / TB;  // one warp per node
    const int GEMM_BLOCKS = NN_PAD / 128;             // 782

    // layer 1: spmm(g_f0=x) -> g_yh ; gemm -> g_f1 (h1, fp16)
    k_spmm<<<SPMM_BLOCKS, TB>>>((const uint2*)pf0);
    k_gemm<128, true, true><<<GEMM_BLOCKS, TB, SMEM128>>>(
        (const uint32_t*)py, (const uint32_t*)pw0, b0, pf1);
    // layer 2: spmm(g_f1) -> g_yh ; gemm -> g_f0 (h2, fp16)
    k_spmm<<<SPMM_BLOCKS, TB>>>((const uint2*)pf1);
    k_gemm<128, true, true><<<GEMM_BLOCKS, TB, SMEM128>>>(
        (const uint32_t*)py, (const uint32_t*)pw1, b1, pf0);
    // layer 3: spmm(g_f0) -> g_yh ; gemm -> d_out (fp32)
    k_spmm<<<SPMM_BLOCKS, TB>>>((const uint2*)pf0);
    k_gemm<64, false, false><<<GEMM_BLOCKS, TB, SMEM64>>>(
        (const uint32_t*)py, (const uint32_t*)pw2, b2, out);
}

// round 11
// speedup vs baseline: 1.7638x; 1.0804x over previous
#include <cuda_runtime.h>
#include <cuda_fp16.h>
#include <cstdint>

#define NN 100000
#define NN_PAD 100096          // 782 * 128
#define NE 1600000
#define SCAN_NB 98             // ceil(NN/1024)

// ---------------- scratch (static __device__ arrays; no allocation) ----------
__device__ __half    g_yh[NN_PAD * 256]; // [N,256] fp16: [spmm(x*ns)*nd | spmm(x)]
__device__ uint2     g_f0[NN * 32];      // [N,128] fp16 features buffer A
__device__ uint2     g_f1[NN * 32];      // [N,128] fp16 features buffer B
__device__ int       g_csr[NE];          // src ids grouped by dst
__device__ int       g_rank[NE];         // per-edge rank within its dst bucket
__device__ int       g_outdeg[NN];
__device__ int       g_indeg[NN];
__device__ uint32_t  g_nsh[NN];          // half2 {ns, ns} pre-packed
__device__ float     g_nd[NN];
__device__ int       g_rowstart[NN + 1];
__device__ int       g_blocksums[128];
__device__ __half    g_wt0[128 * 256];   // [128n][256k] fp16: transposed [w0;rw0]
__device__ __half    g_wt1[128 * 256];   // [128n][256k] fp16: transposed [w1;rw1]
__device__ __half    g_wt2[64 * 256];    // [64n][256k]  fp16: transposed [w2;rw2]

// ---------------- helpers ----------------------------------------------------
__device__ __forceinline__ void mma_f16(float* c, const uint32_t* a, const uint32_t* b) {
    asm volatile(
        "mma.sync.aligned.m16n8k16.row.col.f32.f16.f16.f32 "
        "{%0,%1,%2,%3}, {%4,%5,%6,%7}, {%8,%9}, {%0,%1,%2,%3};\n"
        : "+f"(c[0]), "+f"(c[1]), "+f"(c[2]), "+f"(c[3])
        : "r"(a[0]), "r"(a[1]), "r"(a[2]), "r"(a[3]), "r"(b[0]), "r"(b[1]));
}

__device__ __forceinline__ void cp16(uint32_t dst, const void* src) {
    asm volatile("cp.async.cg.shared.global [%0], [%1], 16;\n" :: "r"(dst), "l"(src));
}
__device__ __forceinline__ void cpcommit() {
    asm volatile("cp.async.commit_group;\n");
}
template <int N>
__device__ __forceinline__ void cpwait() {
    asm volatile("cp.async.wait_group %0;\n" :: "n"(N));
}

// ---------------- fused prep: weights->fp16 transposed, zero degs, x->fp16 ----
__global__ void k_prep(const float4* __restrict__ raw_x,
                       const float* __restrict__ w0, const float* __restrict__ rw0,
                       const float* __restrict__ w1, const float* __restrict__ rw1,
                       const float* __restrict__ w2, const float* __restrict__ rw2) {
    int i = blockIdx.x * blockDim.x + threadIdx.x;
    if (i < 32768) {
        int k = i >> 7, n = i & 127;
        float v = (k < 128) ? w0[k * 128 + n] : rw0[(k - 128) * 128 + n];
        g_wt0[n * 256 + k] = __float2half(v);
    } else if (i < 65536) {
        int j = i - 32768;
        int k = j >> 7, n = j & 127;
        float v = (k < 128) ? w1[k * 128 + n] : rw1[(k - 128) * 128 + n];
        g_wt1[n * 256 + k] = __float2half(v);
    } else if (i < 81920) {
        int j = i - 65536;
        int k = j >> 6, n = j & 63;
        float v = (k < 128) ? w2[k * 64 + n] : rw2[(k - 128) * 64 + n];
        g_wt2[n * 256 + k] = __float2half(v);
    } else if (i < 106920) {
        ((int4*)g_outdeg)[i - 81920] = make_int4(0, 0, 0, 0);
    } else if (i < 131920) {
        ((int4*)g_indeg)[i - 106920] = make_int4(0, 0, 0, 0);
    } else if (i < 3331920) {
        int j = i - 131920;                 // float4 index == uint2 index
        float4 v = raw_x[j];
        __half2 h0 = __floats2half2_rn(v.x, v.y);
        __half2 h1 = __floats2half2_rn(v.z, v.w);
        uint2 u;
        u.x = *reinterpret_cast<uint32_t*>(&h0);
        u.y = *reinterpret_cast<uint32_t*>(&h1);
        g_f0[j] = u;
    }
}

// ---------------- degree count + per-edge dst rank ----------------------------
__global__ void k_deg(const int4* __restrict__ src4, const int4* __restrict__ dst4) {
    int e = blockIdx.x * blockDim.x + threadIdx.x;
    if (e < NE / 4) {
        int4 s = src4[e];
        int4 d = dst4[e];
        atomicAdd(&g_outdeg[s.x], 1); atomicAdd(&g_outdeg[s.y], 1);
        atomicAdd(&g_outdeg[s.z], 1); atomicAdd(&g_outdeg[s.w], 1);
        int4 r;
        r.x = atomicAdd(&g_indeg[d.x], 1);
        r.y = atomicAdd(&g_indeg[d.y], 1);
        r.z = atomicAdd(&g_indeg[d.z], 1);
        r.w = atomicAdd(&g_indeg[d.w], 1);
        ((int4*)g_rank)[e] = r;
    }
}

// exclusive scan of g_indeg (per-block) + blocksums + norms
__global__ void k_scan1() {
    __shared__ int sh[1024];
    int t = threadIdx.x;
    int i = blockIdx.x * 1024 + t;
    int v = (i < NN) ? g_indeg[i] : 0;
    sh[t] = v;
    __syncthreads();
    #pragma unroll
    for (int off = 1; off < 1024; off <<= 1) {
        int add = (t >= off) ? sh[t - off] : 0;
        __syncthreads();
        sh[t] += add;
        __syncthreads();
    }
    if (i < NN) {
        g_rowstart[i] = sh[t] - v;  // exclusive within block
        float ns = rsqrtf(fmaxf((float)g_outdeg[i], 1.0f));
        __half2 nsh = __floats2half2_rn(ns, ns);
        g_nsh[i] = *reinterpret_cast<uint32_t*>(&nsh);
        g_nd[i] = rsqrtf(fmaxf((float)v, 1.0f));
    }
    if (t == 1023) g_blocksums[blockIdx.x] = sh[1023];
}

// apply block offsets (Hillis-Steele over blocksums)
__global__ void k_scan23() {
    __shared__ int sh[128];
    int t = threadIdx.x;
    int v = (t < SCAN_NB) ? g_blocksums[t] : 0;
    if (t < 128) sh[t] = v;
    __syncthreads();
    #pragma unroll
    for (int off = 1; off < 128; off <<= 1) {
        int add = (t < 128 && t >= off) ? sh[t - off] : 0;
        __syncthreads();
        if (t < 128) sh[t] += add;
        __syncthreads();
    }
    int i = blockIdx.x * blockDim.x + t;
    if (i < NN) {
        int b = i >> 10;
        int pre = (b > 0) ? sh[b - 1] : 0;
        g_rowstart[i] += pre;
    }
    if (i == 0) g_rowstart[NN] = NE;
}

// atomic-free CSR fill: pos = rowstart[dst] + rank
__global__ void k_csr(const int4* __restrict__ src4, const int4* __restrict__ dst4) {
    int e = blockIdx.x * blockDim.x + threadIdx.x;
    if (e < NE / 4) {
        int4 s = src4[e];
        int4 d = dst4[e];
        int4 r = ((const int4*)g_rank)[e];
        g_csr[g_rowstart[d.x] + r.x] = s.x;
        g_csr[g_rowstart[d.y] + r.y] = s.y;
        g_csr[g_rowstart[d.z] + r.z] = s.z;
        g_csr[g_rowstart[d.w] + r.w] = s.w;
    }
}

// ---------------- SpMM: warp per node, fp16 HFMA2/HADD2 chunk accumulation ----
// Per 8-edge chunk: accumulate in half2 (4 ops/edge), flush to fp32 per chunk.
// Error bound: intra-chunk fp16 adds ~4e-4 relative on aggregate; fp32 across
// chunks keeps it degree-independent.
__device__ __forceinline__ void acc_h2(uint2 u, uint32_t nh,
                                       uint32_t& h1a, uint32_t& h1b,
                                       uint32_t& h2a, uint32_t& h2b) {
    asm("fma.rn.f16x2 %0, %1, %2, %0;" : "+r"(h1a) : "r"(u.x), "r"(nh));
    asm("fma.rn.f16x2 %0, %1, %2, %0;" : "+r"(h1b) : "r"(u.y), "r"(nh));
    asm("add.rn.f16x2 %0, %0, %1;" : "+r"(h2a) : "r"(u.x));
    asm("add.rn.f16x2 %0, %0, %1;" : "+r"(h2b) : "r"(u.y));
}

__device__ __forceinline__ void flush_h2(uint32_t h, float& f0, float& f1) {
    float2 t = __half22float2(*reinterpret_cast<__half2*>(&h));
    f0 += t.x; f1 += t.y;
}

__global__ __launch_bounds__(256) void k_spmm(const uint2* __restrict__ x) {
    int w    = (blockIdx.x * 256 + threadIdx.x) >> 5;
    int lane = threadIdx.x & 31;
    if (w >= NN) return;
    int s = g_rowstart[w];
    int e = g_rowstart[w + 1];
    float a1[4] = {0.f, 0.f, 0.f, 0.f};
    float a2[4] = {0.f, 0.f, 0.f, 0.f};
    int p = s;
    for (; p + 7 < e; p += 8) {
        int      j[8];
        uint32_t n[8];
        uint2    u[8];
        #pragma unroll
        for (int q = 0; q < 8; ++q) j[q] = g_csr[p + q];
        #pragma unroll
        for (int q = 0; q < 8; ++q) n[q] = g_nsh[j[q]];
        #pragma unroll
        for (int q = 0; q < 8; ++q) u[q] = x[(size_t)j[q] * 32 + lane];
        uint32_t h1a = 0, h1b = 0, h2a = 0, h2b = 0;   // +0.0h x2 each
        #pragma unroll
        for (int q = 0; q < 8; ++q) acc_h2(u[q], n[q], h1a, h1b, h2a, h2b);
        flush_h2(h1a, a1[0], a1[1]);
        flush_h2(h1b, a1[2], a1[3]);
        flush_h2(h2a, a2[0], a2[1]);
        flush_h2(h2b, a2[2], a2[3]);
    }
    if (p < e) {   // tail (<8 edges) in one fp16 chunk
        uint32_t h1a = 0, h1b = 0, h2a = 0, h2b = 0;
        for (; p < e; ++p) {
            int j0 = g_csr[p];
            uint32_t n0 = g_nsh[j0];
            uint2 u0 = x[(size_t)j0 * 32 + lane];
            acc_h2(u0, n0, h1a, h1b, h2a, h2b);
        }
        flush_h2(h1a, a1[0], a1[1]);
        flush_h2(h1b, a1[2], a1[3]);
        flush_h2(h2a, a2[0], a2[1]);
        flush_h2(h2b, a2[2], a2[3]);
    }
    float nd = g_nd[w];
    __half2 p0 = __floats2half2_rn(a1[0] * nd, a1[1] * nd);
    __half2 p1 = __floats2half2_rn(a1[2] * nd, a1[3] * nd);
    __half2 p2 = __floats2half2_rn(a2[0], a2[1]);
    __half2 p3 = __floats2half2_rn(a2[2], a2[3]);
    uint2 o1, o2;
    o1.x = *reinterpret_cast<uint32_t*>(&p0);
    o1.y = *reinterpret_cast<uint32_t*>(&p1);
    o2.x = *reinterpret_cast<uint32_t*>(&p2);
    o2.y = *reinterpret_cast<uint32_t*>(&p3);
    uint2* yp = (uint2*)g_yh;
    yp[(size_t)w * 64 + lane]      = o1;
    yp[(size_t)w * 64 + 32 + lane] = o2;
}

// ---------------- GEMM: C[M,BN] = A[M,256] @ Bt[BN,256]^T + bias (fp16 mma) ---
template <int BN, bool RELU, bool HALFOUT>
__global__ __launch_bounds__(256) void k_gemm(
    const uint32_t* __restrict__ A, const uint32_t* __restrict__ Bw,
    const float* __restrict__ bias, void* __restrict__ Cv)
{
    constexpr int BM = 128;
    constexpr int AS = 36;                 // stage row stride in words (64h + pad)
    constexpr int ASTG = BM * AS;
    constexpr int BSTG = BN * AS;
    constexpr int NT = BN / 16;            // n-tiles per warp (warp n-span BN/2)
    constexpr int NKC = 4;                 // 256 / 64 chunks

    extern __shared__ uint32_t dyn[];
    uint32_t* sA = dyn;
    uint32_t* sB = dyn + 2 * ASTG;
    const uint32_t saddrA = (uint32_t)__cvta_generic_to_shared(sA);
    const uint32_t saddrB = (uint32_t)__cvta_generic_to_shared(sB);

    const int tid  = threadIdx.x;
    const int warp = tid >> 5, lane = tid & 31;
    const int grp  = lane >> 2, tig = lane & 3;
    const int wm   = (warp >> 1) * 32;
    const int wn   = (warp & 1) * (BN / 2);
    const int blockRow = blockIdx.x * BM;

    auto stage = [&](int kc, int buf) {
        #pragma unroll
        for (int it = 0; it < 4; ++it) {       // A chunk: 128 rows x 64 halves
            int idx = tid + it * 256;
            int r = idx >> 3, c = idx & 7;
            cp16(saddrA + (uint32_t)(buf * ASTG + r * AS + c * 4) * 4,
                 A + (size_t)(blockRow + r) * 128 + kc * 32 + c * 4);
        }
        #pragma unroll
        for (int it = 0; it < BN / 32; ++it) { // B chunk: BN rows x 64 halves
            int idx = tid + it * 256;
            int r = idx >> 3, c = idx & 7;
            cp16(saddrB + (uint32_t)(buf * BSTG + r * AS + c * 4) * 4,
                 Bw + (size_t)r * 128 + kc * 32 + c * 4);
        }
        cpcommit();
    };

    float acc[2][NT][4];
    #pragma unroll
    for (int mt = 0; mt < 2; mt++)
        #pragma unroll
        for (int nt = 0; nt < NT; nt++)
            #pragma unroll
            for (int r = 0; r < 4; r++) acc[mt][nt][r] = 0.f;

    stage(0, 0);
    #pragma unroll
    for (int kc = 0; kc < NKC; ++kc) {
        int buf = kc & 1;
        if (kc + 1 < NKC) {
            stage(kc + 1, buf ^ 1);
            cpwait<1>();
        } else {
            cpwait<0>();
        }
        __syncthreads();

        const uint32_t* cA = sA + buf * ASTG;
        const uint32_t* cB = sB + buf * BSTG;
        #pragma unroll
        for (int ks = 0; ks < 4; ++ks) {       // 4 x k16 per 64-half chunk
            uint32_t af[2][4];
            #pragma unroll
            for (int mt = 0; mt < 2; mt++) {
                int row = wm + mt * 16 + grp;
                int ko = ks * 8 + tig;
                af[mt][0] = cA[row * AS + ko];
                af[mt][1] = cA[(row + 8) * AS + ko];
                af[mt][2] = cA[row * AS + ko + 4];
                af[mt][3] = cA[(row + 8) * AS + ko + 4];
            }
            uint32_t bf[NT][2];
            #pragma unroll
            for (int nt = 0; nt < NT; nt++) {
                int col = wn + nt * 8 + grp;
                int ko = ks * 8 + tig;
                bf[nt][0] = cB[col * AS + ko];
                bf[nt][1] = cB[col * AS + ko + 4];
            }
            #pragma unroll
            for (int mt = 0; mt < 2; mt++)
                #pragma unroll
                for (int nt = 0; nt < NT; nt++)
                    mma_f16(acc[mt][nt], af[mt], bf[nt]);
        }
        __syncthreads();
    }

    // epilogue: bias (+relu), half2 or float2 stores
    #pragma unroll
    for (int mt = 0; mt < 2; ++mt) {
        int r0 = blockRow + wm + mt * 16 + grp;
        int r1 = r0 + 8;
        #pragma unroll
        for (int nt = 0; nt < NT; ++nt) {
            int col = wn + nt * 8 + 2 * tig;
            float b0v = bias[col], b1v = bias[col + 1];
            float v0 = acc[mt][nt][0] + b0v;
            float v1 = acc[mt][nt][1] + b1v;
            float v2 = acc[mt][nt][2] + b0v;
            float v3 = acc[mt][nt][3] + b1v;
            if (RELU) {
                v0 = fmaxf(v0, 0.f); v1 = fmaxf(v1, 0.f);
                v2 = fmaxf(v2, 0.f); v3 = fmaxf(v3, 0.f);
            }
            if (HALFOUT) {
                __half* C = (__half*)Cv;
                if (r0 < NN)
                    *reinterpret_cast<__half2*>(&C[(size_t)r0 * BN + col]) =
                        __floats2half2_rn(v0, v1);
                if (r1 < NN)
                    *reinterpret_cast<__half2*>(&C[(size_t)r1 * BN + col]) =
                        __floats2half2_rn(v2, v3);
            } else {
                float* C = (float*)Cv;
                if (r0 < NN)
                    *reinterpret_cast<float2*>(&C[(size_t)r0 * BN + col]) = make_float2(v0, v1);
                if (r1 < NN)
                    *reinterpret_cast<float2*>(&C[(size_t)r1 * BN + col]) = make_float2(v2, v3);
            }
        }
    }
}

// ---------------- launcher ----------------------------------------------------
extern "C" void kernel_launch(void* const* d_in, const int* in_sizes, int n_in,
                              void* d_out, int out_size) {
    const float* raw_x = (const float*)d_in[0];
    const int*   src   = (const int*)d_in[1];
    const int*   dst   = (const int*)d_in[2];
    const float* w0    = (const float*)d_in[3];
    const float* b0    = (const float*)d_in[4];
    const float* w1    = (const float*)d_in[5];
    const float* b1    = (const float*)d_in[6];
    const float* w2    = (const float*)d_in[7];
    const float* b2    = (const float*)d_in[8];
    const float* rw0   = (const float*)d_in[9];
    const float* rw1   = (const float*)d_in[10];
    const float* rw2   = (const float*)d_in[11];
    float* out = (float*)d_out;

    void *py = nullptr, *pf0 = nullptr, *pf1 = nullptr;
    void *pw0 = nullptr, *pw1 = nullptr, *pw2 = nullptr;
    cudaGetSymbolAddress(&py, g_yh);
    cudaGetSymbolAddress(&pf0, g_f0);
    cudaGetSymbolAddress(&pf1, g_f1);
    cudaGetSymbolAddress(&pw0, g_wt0);
    cudaGetSymbolAddress(&pw1, g_wt1);
    cudaGetSymbolAddress(&pw2, g_wt2);

    constexpr int SMEM128 = 2 * (128 * 36 + 128 * 36) * 4;  // 73728
    constexpr int SMEM64  = 2 * (128 * 36 + 64 * 36) * 4;   // 55296
    cudaFuncSetAttribute(k_gemm<128, true, true>,
                         cudaFuncAttributeMaxDynamicSharedMemorySize, SMEM128);
    cudaFuncSetAttribute(k_gemm<64, false, false>,
                         cudaFuncAttributeMaxDynamicSharedMemorySize, SMEM64);

    const int TB = 256;
    k_prep<<<(3331920 + TB - 1) / TB, TB>>>((const float4*)raw_x,
                                            w0, rw0, w1, rw1, w2, rw2);
    k_deg<<<(NE / 4 + TB - 1) / TB, TB>>>((const int4*)src, (const int4*)dst);
    k_scan1<<<SCAN_NB, 1024>>>();
    k_scan23<<<(NN + TB - 1) / TB, TB>>>();
    k_csr<<<(NE / 4 + TB - 1) / TB, TB>>>((const int4*)src, (const int4*)dst);

    const int SPMM_BLOCKS = (NN * 32 + TB - 1) / TB;  // one warp per node
    const int GEMM_BLOCKS = NN_PAD / 128;             // 782

    // layer 1: spmm(g_f0=x) -> g_yh ; gemm -> g_f1 (h1, fp16)
    k_spmm<<<SPMM_BLOCKS, TB>>>((const uint2*)pf0);
    k_gemm<128, true, true><<<GEMM_BLOCKS, TB, SMEM128>>>(
        (const uint32_t*)py, (const uint32_t*)pw0, b0, pf1);
    // layer 2: spmm(g_f1) -> g_yh ; gemm -> g_f0 (h2, fp16)
    k_spmm<<<SPMM_BLOCKS, TB>>>((const uint2*)pf1);
    k_gemm<128, true, true><<<GEMM_BLOCKS, TB, SMEM128>>>(
        (const uint32_t*)py, (const uint32_t*)pw1, b1, pf0);
    // layer 3: spmm(g_f0) -> g_yh ; gemm -> d_out (fp32)
    k_spmm<<<SPMM_BLOCKS, TB>>>((const uint2*)pf0);
    k_gemm<64, false, false><<<GEMM_BLOCKS, TB, SMEM64>>>(
        (const uint32_t*)py, (const uint32_t*)pw2, b2, out);
}

// round 12
// speedup vs baseline: 1.7761x; 1.0070x over previous
#include <cuda_runtime.h>
#include <cuda_fp16.h>
#include <cstdint>

#define NN 100000
#define NN_PAD 100096          // 782 * 128
#define NE 1600000
#define SCAN_NB 98             // ceil(NN/1024)

// ---------------- scratch (static __device__ arrays; no allocation) ----------
// NOTE: g_outdeg/g_indeg must be ZERO at entry. Module load zero-inits them;
// the layer-3 GEMM re-zeroes them at the end of every call (deterministic).
// g_scan_cnt is likewise self-resetting (last scan block writes 0).
__device__ __half    g_yh[NN_PAD * 256]; // [N,256] fp16: [spmm(x*ns)*nd | spmm(x)]
__device__ uint2     g_f0[NN * 32];      // [N,128] fp16 features buffer A
__device__ uint2     g_f1[NN * 32];      // [N,128] fp16 features buffer B
__device__ int       g_csr[NE];          // src ids grouped by dst
__device__ int       g_rank[NE];         // per-edge rank within its dst bucket
__device__ int       g_outdeg[NN];
__device__ int       g_indeg[NN];
__device__ float     g_ns[NN];
__device__ float     g_nd[NN];
__device__ int       g_rowstart[NN + 1]; // block-LOCAL exclusive scan of indeg
__device__ int       g_blocksums[128];
__device__ int       g_pre[128];         // global exclusive block offsets
__device__ int       g_scan_cnt;
__device__ __half    g_wt0[128 * 256];   // [128n][256k] fp16: transposed [w0;rw0]
__device__ __half    g_wt1[128 * 256];   // [128n][256k] fp16: transposed [w1;rw1]
__device__ __half    g_wt2[64 * 256];    // [64n][256k]  fp16: transposed [w2;rw2]

// ---------------- helpers ----------------------------------------------------
__device__ __forceinline__ void mma_f16(float* c, const uint32_t* a, const uint32_t* b) {
    asm volatile(
        "mma.sync.aligned.m16n8k16.row.col.f32.f16.f16.f32 "
        "{%0,%1,%2,%3}, {%4,%5,%6,%7}, {%8,%9}, {%0,%1,%2,%3};\n"
        : "+f"(c[0]), "+f"(c[1]), "+f"(c[2]), "+f"(c[3])
        : "r"(a[0]), "r"(a[1]), "r"(a[2]), "r"(a[3]), "r"(b[0]), "r"(b[1]));
}

__device__ __forceinline__ void cp16(uint32_t dst, const void* src) {
    asm volatile("cp.async.cg.shared.global [%0], [%1], 16;\n" :: "r"(dst), "l"(src));
}
__device__ __forceinline__ void cpcommit() {
    asm volatile("cp.async.commit_group;\n");
}
template <int N>
__device__ __forceinline__ void cpwait() {
    asm volatile("cp.async.wait_group %0;\n" :: "n"(N));
}

// ---------------- launch 0: weights->fp16T + deg/rank + x->fp16 ---------------
// work ranges: [0,81920) weights | [81920,481920) deg+rank | [481920,3681920) x
__global__ void k_prepdeg(const float4* __restrict__ raw_x,
                          const int4* __restrict__ src4, const int4* __restrict__ dst4,
                          const float* __restrict__ w0, const float* __restrict__ rw0,
                          const float* __restrict__ w1, const float* __restrict__ rw1,
                          const float* __restrict__ w2, const float* __restrict__ rw2) {
    int i = blockIdx.x * blockDim.x + threadIdx.x;
    if (i < 32768) {
        int k = i >> 7, n = i & 127;
        float v = (k < 128) ? w0[k * 128 + n] : rw0[(k - 128) * 128 + n];
        g_wt0[n * 256 + k] = __float2half(v);
    } else if (i < 65536) {
        int j = i - 32768;
        int k = j >> 7, n = j & 127;
        float v = (k < 128) ? w1[k * 128 + n] : rw1[(k - 128) * 128 + n];
        g_wt1[n * 256 + k] = __float2half(v);
    } else if (i < 81920) {
        int j = i - 65536;
        int k = j >> 6, n = j & 63;
        float v = (k < 128) ? w2[k * 64 + n] : rw2[(k - 128) * 64 + n];
        g_wt2[n * 256 + k] = __float2half(v);
    } else if (i < 481920) {
        int e = i - 81920;                  // edge quad index, < NE/4
        int4 s = src4[e];
        int4 d = dst4[e];
        atomicAdd(&g_outdeg[s.x], 1); atomicAdd(&g_outdeg[s.y], 1);
        atomicAdd(&g_outdeg[s.z], 1); atomicAdd(&g_outdeg[s.w], 1);
        int4 r;
        r.x = atomicAdd(&g_indeg[d.x], 1);
        r.y = atomicAdd(&g_indeg[d.y], 1);
        r.z = atomicAdd(&g_indeg[d.z], 1);
        r.w = atomicAdd(&g_indeg[d.w], 1);
        ((int4*)g_rank)[e] = r;
    } else if (i < 3681920) {
        int j = i - 481920;                 // float4 index == uint2 index
        float4 v = raw_x[j];
        __half2 h0 = __floats2half2_rn(v.x, v.y);
        __half2 h1 = __floats2half2_rn(v.z, v.w);
        uint2 u;
        u.x = *reinterpret_cast<uint32_t*>(&h0);
        u.y = *reinterpret_cast<uint32_t*>(&h1);
        g_f0[j] = u;
    }
}

// ---------------- launch 1: block-local scan + norms + last-block finalize ----
__global__ void k_scan1() {
    __shared__ int sh[1024];
    __shared__ int last;
    int t = threadIdx.x;
    int i = blockIdx.x * 1024 + t;
    int v = (i < NN) ? g_indeg[i] : 0;
    sh[t] = v;
    if (t == 0) last = 0;
    __syncthreads();
    #pragma unroll
    for (int off = 1; off < 1024; off <<= 1) {
        int add = (t >= off) ? sh[t - off] : 0;
        __syncthreads();
        sh[t] += add;
        __syncthreads();
    }
    if (i < NN) {
        g_rowstart[i] = sh[t] - v;  // exclusive within block
        g_ns[i] = rsqrtf(fmaxf((float)g_outdeg[i], 1.0f));
        g_nd[i] = rsqrtf(fmaxf((float)v, 1.0f));
    }
    if (t == 1023) {
        g_blocksums[blockIdx.x] = sh[1023];
        __threadfence();
        int old = atomicAdd(&g_scan_cnt, 1);
        if (old == SCAN_NB - 1) last = 1;
    }
    __syncthreads();
    if (last) {
        __threadfence();
        int b = (t < SCAN_NB) ? *((volatile int*)&g_blocksums[t]) : 0;
        if (t < 128) sh[t] = b;
        __syncthreads();
        #pragma unroll
        for (int off = 1; off < 128; off <<= 1) {
            int add = (t < 128 && t >= off) ? sh[t - off] : 0;
            __syncthreads();
            if (t < 128) sh[t] += add;
            __syncthreads();
        }
        if (t < 128) g_pre[t] = (t < SCAN_NB) ? (sh[t] - b) : NE;  // exclusive
        if (t == 0) g_scan_cnt = 0;   // self-reset for next invocation
    }
}

// ---------------- launch 2: CSR fill (atomic-free) ----------------------------
__global__ void k_csr(const int4* __restrict__ src4, const int4* __restrict__ dst4) {
    int e = blockIdx.x * blockDim.x + threadIdx.x;
    if (e < NE / 4) {
        int4 s = src4[e];
        int4 d = dst4[e];
        int4 r = ((const int4*)g_rank)[e];
        g_csr[g_rowstart[d.x] + g_pre[d.x >> 10] + r.x] = s.x;
        g_csr[g_rowstart[d.y] + g_pre[d.y >> 10] + r.y] = s.y;
        g_csr[g_rowstart[d.z] + g_pre[d.z >> 10] + r.z] = s.z;
        g_csr[g_rowstart[d.w] + g_pre[d.w >> 10] + r.w] = s.w;
    }
}

// ---------------- launch 3 (PROFILED): SpMM, warp/node, unroll 4, fp32 accum --
// MLP_p1 = 4 (was 8): per the B300 multi-CTA spread model, halving the
// front-batched LDG count cuts cross-CTA L1tex-queue spread (spr 2.3 -> ~1.5).
__device__ __forceinline__ void acc_edge(uint2 u, float n, float* a1, float* a2) {
    float2 f0 = __half22float2(*reinterpret_cast<__half2*>(&u.x));
    float2 f1 = __half22float2(*reinterpret_cast<__half2*>(&u.y));
    a2[0] += f0.x; a2[1] += f0.y; a2[2] += f1.x; a2[3] += f1.y;
    a1[0] = fmaf(f0.x, n, a1[0]); a1[1] = fmaf(f0.y, n, a1[1]);
    a1[2] = fmaf(f1.x, n, a1[2]); a1[3] = fmaf(f1.y, n, a1[3]);
}

__global__ __launch_bounds__(256) void k_spmm(const uint2* __restrict__ x) {
    int w    = (blockIdx.x * 256 + threadIdx.x) >> 5;
    int lane = threadIdx.x & 31;
    if (w >= NN) return;
    int s = g_rowstart[w] + g_pre[w >> 10];
    int e = (w + 1 < NN) ? (g_rowstart[w + 1] + g_pre[(w + 1) >> 10]) : NE;
    float a1[4] = {0.f, 0.f, 0.f, 0.f};
    float a2[4] = {0.f, 0.f, 0.f, 0.f};
    int p = s;
    for (; p + 3 < e; p += 4) {
        int   j[4];
        float n[4];
        uint2 u[4];
        #pragma unroll
        for (int q = 0; q < 4; ++q) j[q] = g_csr[p + q];
        #pragma unroll
        for (int q = 0; q < 4; ++q) n[q] = g_ns[j[q]];
        #pragma unroll
        for (int q = 0; q < 4; ++q) u[q] = x[(size_t)j[q] * 32 + lane];
        #pragma unroll
        for (int q = 0; q < 4; ++q) acc_edge(u[q], n[q], a1, a2);
    }
    for (; p < e; ++p) {
        int j0 = g_csr[p];
        float n0 = g_ns[j0];
        uint2 u0 = x[(size_t)j0 * 32 + lane];
        acc_edge(u0, n0, a1, a2);
    }
    float nd = g_nd[w];
    __half2 p0 = __floats2half2_rn(a1[0] * nd, a1[1] * nd);
    __half2 p1 = __floats2half2_rn(a1[2] * nd, a1[3] * nd);
    __half2 p2 = __floats2half2_rn(a2[0], a2[1]);
    __half2 p3 = __floats2half2_rn(a2[2], a2[3]);
    uint2 o1, o2;
    o1.x = *reinterpret_cast<uint32_t*>(&p0);
    o1.y = *reinterpret_cast<uint32_t*>(&p1);
    o2.x = *reinterpret_cast<uint32_t*>(&p2);
    o2.y = *reinterpret_cast<uint32_t*>(&p3);
    uint2* yp = (uint2*)g_yh;
    yp[(size_t)w * 64 + lane]      = o1;
    yp[(size_t)w * 64 + 32 + lane] = o2;
}

// ---------------- GEMM: C[M,BN] = A[M,256] @ Bt[BN,256]^T + bias (fp16 mma) ---
// CLEAN: re-zero degree arrays for the next invocation (layer 3 only).
template <int BN, bool RELU, bool HALFOUT, bool CLEAN>
__global__ __launch_bounds__(256) void k_gemm(
    const uint32_t* __restrict__ A, const uint32_t* __restrict__ Bw,
    const float* __restrict__ bias, void* __restrict__ Cv)
{
    constexpr int BM = 128;
    constexpr int AS = 36;                 // stage row stride in words (64h + pad)
    constexpr int ASTG = BM * AS;
    constexpr int BSTG = BN * AS;
    constexpr int NT = BN / 16;            // n-tiles per warp (warp n-span BN/2)
    constexpr int NKC = 4;                 // 256 / 64 chunks

    if (CLEAN) {
        int idx = blockIdx.x * 256 + threadIdx.x;
        if (idx < 25000)      ((int4*)g_outdeg)[idx] = make_int4(0, 0, 0, 0);
        else if (idx < 50000) ((int4*)g_indeg)[idx - 25000] = make_int4(0, 0, 0, 0);
    }

    extern __shared__ uint32_t dyn[];
    uint32_t* sA = dyn;
    uint32_t* sB = dyn + 2 * ASTG;
    const uint32_t saddrA = (uint32_t)__cvta_generic_to_shared(sA);
    const uint32_t saddrB = (uint32_t)__cvta_generic_to_shared(sB);

    const int tid  = threadIdx.x;
    const int warp = tid >> 5, lane = tid & 31;
    const int grp  = lane >> 2, tig = lane & 3;
    const int wm   = (warp >> 1) * 32;
    const int wn   = (warp & 1) * (BN / 2);
    const int blockRow = blockIdx.x * BM;

    auto stage = [&](int kc, int buf) {
        #pragma unroll
        for (int it = 0; it < 4; ++it) {       // A chunk: 128 rows x 64 halves
            int idx = tid + it * 256;
            int r = idx >> 3, c = idx & 7;
            cp16(saddrA + (uint32_t)(buf * ASTG + r * AS + c * 4) * 4,
                 A + (size_t)(blockRow + r) * 128 + kc * 32 + c * 4);
        }
        #pragma unroll
        for (int it = 0; it < BN / 32; ++it) { // B chunk: BN rows x 64 halves
            int idx = tid + it * 256;
            int r = idx >> 3, c = idx & 7;
            cp16(saddrB + (uint32_t)(buf * BSTG + r * AS + c * 4) * 4,
                 Bw + (size_t)r * 128 + kc * 32 + c * 4);
        }
        cpcommit();
    };

    float acc[2][NT][4];
    #pragma unroll
    for (int mt = 0; mt < 2; mt++)
        #pragma unroll
        for (int nt = 0; nt < NT; nt++)
            #pragma unroll
            for (int r = 0; r < 4; r++) acc[mt][nt][r] = 0.f;

    stage(0, 0);
    #pragma unroll
    for (int kc = 0; kc < NKC; ++kc) {
        int buf = kc & 1;
        if (kc + 1 < NKC) {
            stage(kc + 1, buf ^ 1);
            cpwait<1>();
        } else {
            cpwait<0>();
        }
        __syncthreads();

        const uint32_t* cA = sA + buf * ASTG;
        const uint32_t* cB = sB + buf * BSTG;
        #pragma unroll
        for (int ks = 0; ks < 4; ++ks) {       // 4 x k16 per 64-half chunk
            uint32_t af[2][4];
            #pragma unroll
            for (int mt = 0; mt < 2; mt++) {
                int row = wm + mt * 16 + grp;
                int ko = ks * 8 + tig;
                af[mt][0] = cA[row * AS + ko];
                af[mt][1] = cA[(row + 8) * AS + ko];
                af[mt][2] = cA[row * AS + ko + 4];
                af[mt][3] = cA[(row + 8) * AS + ko + 4];
            }
            uint32_t bf[NT][2];
            #pragma unroll
            for (int nt = 0; nt < NT; nt++) {
                int col = wn + nt * 8 + grp;
                int ko = ks * 8 + tig;
                bf[nt][0] = cB[col * AS + ko];
                bf[nt][1] = cB[col * AS + ko + 4];
            }
            #pragma unroll
            for (int mt = 0; mt < 2; mt++)
                #pragma unroll
                for (int nt = 0; nt < NT; nt++)
                    mma_f16(acc[mt][nt], af[mt], bf[nt]);
        }
        __syncthreads();
    }

    // epilogue: bias (+relu), half2 or float2 stores
    #pragma unroll
    for (int mt = 0; mt < 2; ++mt) {
        int r0 = blockRow + wm + mt * 16 + grp;
        int r1 = r0 + 8;
        #pragma unroll
        for (int nt = 0; nt < NT; ++nt) {
            int col = wn + nt * 8 + 2 * tig;
            float b0v = bias[col], b1v = bias[col + 1];
            float v0 = acc[mt][nt][0] + b0v;
            float v1 = acc[mt][nt][1] + b1v;
            float v2 = acc[mt][nt][2] + b0v;
            float v3 = acc[mt][nt][3] + b1v;
            if (RELU) {
                v0 = fmaxf(v0, 0.f); v1 = fmaxf(v1, 0.f);
                v2 = fmaxf(v2, 0.f); v3 = fmaxf(v3, 0.f);
            }
            if (HALFOUT) {
                __half* C = (__half*)Cv;
                if (r0 < NN)
                    *reinterpret_cast<__half2*>(&C[(size_t)r0 * BN + col]) =
                        __floats2half2_rn(v0, v1);
                if (r1 < NN)
                    *reinterpret_cast<__half2*>(&C[(size_t)r1 * BN + col]) =
                        __floats2half2_rn(v2, v3);
            } else {
                float* C = (float*)Cv;
                if (r0 < NN)
                    *reinterpret_cast<float2*>(&C[(size_t)r0 * BN + col]) = make_float2(v0, v1);
                if (r1 < NN)
                    *reinterpret_cast<float2*>(&C[(size_t)r1 * BN + col]) = make_float2(v2, v3);
            }
        }
    }
}

// ---------------- launcher ----------------------------------------------------
extern "C" void kernel_launch(void* const* d_in, const int* in_sizes, int n_in,
                              void* d_out, int out_size) {
    const float* raw_x = (const float*)d_in[0];
    const int*   src   = (const int*)d_in[1];
    const int*   dst   = (const int*)d_in[2];
    const float* w0    = (const float*)d_in[3];
    const float* b0    = (const float*)d_in[4];
    const float* w1    = (const float*)d_in[5];
    const float* b1    = (const float*)d_in[6];
    const float* w2    = (const float*)d_in[7];
    const float* b2    = (const float*)d_in[8];
    const float* rw0   = (const float*)d_in[9];
    const float* rw1   = (const float*)d_in[10];
    const float* rw2   = (const float*)d_in[11];
    float* out = (float*)d_out;

    void *py = nullptr, *pf0 = nullptr, *pf1 = nullptr;
    void *pw0 = nullptr, *pw1 = nullptr, *pw2 = nullptr;
    cudaGetSymbolAddress(&py, g_yh);
    cudaGetSymbolAddress(&pf0, g_f0);
    cudaGetSymbolAddress(&pf1, g_f1);
    cudaGetSymbolAddress(&pw0, g_wt0);
    cudaGetSymbolAddress(&pw1, g_wt1);
    cudaGetSymbolAddress(&pw2, g_wt2);

    constexpr int SMEM128 = 2 * (128 * 36 + 128 * 36) * 4;  // 73728
    constexpr int SMEM64  = 2 * (128 * 36 + 64 * 36) * 4;   // 55296
    cudaFuncSetAttribute(k_gemm<128, true, true, false>,
                         cudaFuncAttributeMaxDynamicSharedMemorySize, SMEM128);
    cudaFuncSetAttribute(k_gemm<64, false, false, true>,
                         cudaFuncAttributeMaxDynamicSharedMemorySize, SMEM64);

    const int TB = 256;
    // launch 0: weights + deg/rank + x conversion (degs pre-zeroed, see note)
    k_prepdeg<<<(3681920 + TB - 1) / TB, TB>>>(
        (const float4*)raw_x, (const int4*)src, (const int4*)dst,
        w0, rw0, w1, rw1, w2, rw2);
    // launch 1: block-local scan + norms + last-block global prefix
    k_scan1<<<SCAN_NB, 1024>>>();
    // launch 2: CSR fill
    k_csr<<<(NE / 4 + TB - 1) / TB, TB>>>((const int4*)src, (const int4*)dst);

    const int SPMM_BLOCKS = (NN * 32 + TB - 1) / TB;  // one warp per node
    const int GEMM_BLOCKS = NN_PAD / 128;             // 782

    // launch 3 (profiled): layer 1 spmm
    k_spmm<<<SPMM_BLOCKS, TB>>>((const uint2*)pf0);
    k_gemm<128, true, true, false><<<GEMM_BLOCKS, TB, SMEM128>>>(
        (const uint32_t*)py, (const uint32_t*)pw0, b0, pf1);
    // layer 2
    k_spmm<<<SPMM_BLOCKS, TB>>>((const uint2*)pf1);
    k_gemm<128, true, true, false><<<GEMM_BLOCKS, TB, SMEM128>>>(
        (const uint32_t*)py, (const uint32_t*)pw1, b1, pf0);
    // layer 3 (+ degree re-zero for next call)
    k_spmm<<<SPMM_BLOCKS, TB>>>((const uint2*)pf0);
    k_gemm<64, false, false, true><<<GEMM_BLOCKS, TB, SMEM64>>>(
        (const uint32_t*)py, (const uint32_t*)pw2, b2, out);
}

// round 13
// speedup vs baseline: 1.7838x; 1.0043x over previous
#include <cuda_runtime.h>
#include <cuda_fp16.h>
#include <cstdint>

#define NN 100000
#define NN_PAD 100096          // 782 * 128
#define NE 1600000
#define SCAN_NB 98             // ceil(NN/1024)

// ---------------- scratch (static __device__ arrays; no allocation) ----------
__device__ __half g_yh[NN_PAD * 256]; // [N,256] fp16: [spmm(x*ns)*nd | spmm(x)]
__device__ uint2  g_f0[NN * 32];      // [N,128] fp16 features buffer A
__device__ uint2  g_f1[NN * 32];      // [N,128] fp16 features buffer B
__device__ int    g_csr[NE];          // src ids grouped by dst
__device__ int    g_rank[NE];         // per-edge rank within its dst bucket
__device__ int    g_outdeg[NN];
__device__ int    g_indeg[NN];
__device__ float  g_ns[NN];
__device__ float  g_nd[NN];
__device__ int    g_rowstart[NN + 1];
__device__ int    g_blocksums[128];
__device__ __half g_wt0[128 * 256];   // [128n][256k] fp16: transposed [w0;rw0]
__device__ __half g_wt1[128 * 256];   // [128n][256k] fp16: transposed [w1;rw1]
__device__ __half g_wt2[64 * 256];    // [64n][256k]  fp16: transposed [w2;rw2]

// ---------------- helpers ----------------------------------------------------
__device__ __forceinline__ void mma_f16(float* c, const uint32_t* a, const uint32_t* b) {
    asm volatile(
        "mma.sync.aligned.m16n8k16.row.col.f32.f16.f16.f32 "
        "{%0,%1,%2,%3}, {%4,%5,%6,%7}, {%8,%9}, {%0,%1,%2,%3};\n"
        : "+f"(c[0]), "+f"(c[1]), "+f"(c[2]), "+f"(c[3])
        : "r"(a[0]), "r"(a[1]), "r"(a[2]), "r"(a[3]), "r"(b[0]), "r"(b[1]));
}

__device__ __forceinline__ void cp16(uint32_t dst, const void* src) {
    asm volatile("cp.async.cg.shared.global [%0], [%1], 16;\n" :: "r"(dst), "l"(src));
}
__device__ __forceinline__ void cpcommit() {
    asm volatile("cp.async.commit_group;\n");
}
template <int N>
__device__ __forceinline__ void cpwait() {
    asm volatile("cp.async.wait_group %0;\n" :: "n"(N));
}

// ---------------- fused prep: weights->fp16 transposed, zero degs, x->fp16 ----
__global__ void k_prep(const float4* __restrict__ raw_x,
                       const float* __restrict__ w0, const float* __restrict__ rw0,
                       const float* __restrict__ w1, const float* __restrict__ rw1,
                       const float* __restrict__ w2, const float* __restrict__ rw2) {
    int i = blockIdx.x * blockDim.x + threadIdx.x;
    if (i < 32768) {
        int k = i >> 7, n = i & 127;
        float v = (k < 128) ? w0[k * 128 + n] : rw0[(k - 128) * 128 + n];
        g_wt0[n * 256 + k] = __float2half(v);
    } else if (i < 65536) {
        int j = i - 32768;
        int k = j >> 7, n = j & 127;
        float v = (k < 128) ? w1[k * 128 + n] : rw1[(k - 128) * 128 + n];
        g_wt1[n * 256 + k] = __float2half(v);
    } else if (i < 81920) {
        int j = i - 65536;
        int k = j >> 6, n = j & 63;
        float v = (k < 128) ? w2[k * 64 + n] : rw2[(k - 128) * 64 + n];
        g_wt2[n * 256 + k] = __float2half(v);
    } else if (i < 106920) {
        ((int4*)g_outdeg)[i - 81920] = make_int4(0, 0, 0, 0);
    } else if (i < 131920) {
        ((int4*)g_indeg)[i - 106920] = make_int4(0, 0, 0, 0);
    } else if (i < 3331920) {
        int j = i - 131920;                 // float4 index == uint2 index
        float4 v = raw_x[j];
        __half2 h0 = __floats2half2_rn(v.x, v.y);
        __half2 h1 = __floats2half2_rn(v.z, v.w);
        uint2 u;
        u.x = *reinterpret_cast<uint32_t*>(&h0);
        u.y = *reinterpret_cast<uint32_t*>(&h1);
        g_f0[j] = u;
    }
}

// ---------------- degree count + per-edge dst rank ----------------------------
__global__ void k_deg(const int4* __restrict__ src4, const int4* __restrict__ dst4) {
    int e = blockIdx.x * blockDim.x + threadIdx.x;
    if (e < NE / 4) {
        int4 s = src4[e];
        int4 d = dst4[e];
        atomicAdd(&g_outdeg[s.x], 1); atomicAdd(&g_outdeg[s.y], 1);
        atomicAdd(&g_outdeg[s.z], 1); atomicAdd(&g_outdeg[s.w], 1);
        int4 r;
        r.x = atomicAdd(&g_indeg[d.x], 1);
        r.y = atomicAdd(&g_indeg[d.y], 1);
        r.z = atomicAdd(&g_indeg[d.z], 1);
        r.w = atomicAdd(&g_indeg[d.w], 1);
        ((int4*)g_rank)[e] = r;
    }
}

// exclusive scan of g_indeg (per-block) + blocksums + norms
__global__ void k_scan1() {
    __shared__ int sh[1024];
    int t = threadIdx.x;
    int i = blockIdx.x * 1024 + t;
    int v = (i < NN) ? g_indeg[i] : 0;
    sh[t] = v;
    __syncthreads();
    #pragma unroll
    for (int off = 1; off < 1024; off <<= 1) {
        int add = (t >= off) ? sh[t - off] : 0;
        __syncthreads();
        sh[t] += add;
        __syncthreads();
    }
    if (i < NN) {
        g_rowstart[i] = sh[t] - v;  // exclusive within block
        g_ns[i] = rsqrtf(fmaxf((float)g_outdeg[i], 1.0f));
        g_nd[i] = rsqrtf(fmaxf((float)v, 1.0f));
    }
    if (t == 1023) g_blocksums[blockIdx.x] = sh[1023];
}

// apply block offsets (Hillis-Steele over blocksums)
__global__ void k_scan23() {
    __shared__ int sh[128];
    int t = threadIdx.x;
    int v = (t < SCAN_NB) ? g_blocksums[t] : 0;
    if (t < 128) sh[t] = v;
    __syncthreads();
    #pragma unroll
    for (int off = 1; off < 128; off <<= 1) {
        int add = (t < 128 && t >= off) ? sh[t - off] : 0;
        __syncthreads();
        if (t < 128) sh[t] += add;
        __syncthreads();
    }
    int i = blockIdx.x * blockDim.x + t;
    if (i < NN) {
        int b = i >> 10;
        int pre = (b > 0) ? sh[b - 1] : 0;
        g_rowstart[i] += pre;
    }
    if (i == 0) g_rowstart[NN] = NE;
}

// atomic-free CSR fill: pos = rowstart[dst] + rank
__global__ void k_csr(const int4* __restrict__ src4, const int4* __restrict__ dst4) {
    int e = blockIdx.x * blockDim.x + threadIdx.x;
    if (e < NE / 4) {
        int4 s = src4[e];
        int4 d = dst4[e];
        int4 r = ((const int4*)g_rank)[e];
        g_csr[g_rowstart[d.x] + r.x] = s.x;
        g_csr[g_rowstart[d.y] + r.y] = s.y;
        g_csr[g_rowstart[d.z] + r.z] = s.z;
        g_csr[g_rowstart[d.w] + r.w] = s.w;
    }
}

// ---------------- SpMM: warp per node, unroll 4 (spread-optimal), fp32 accum --
// MLP_p1 = 4: per the B300 multi-CTA spread model, this cuts cross-CTA
// L1tex-queue tail vs unroll 8 (measured 66.8 -> 55.8 us in R12).
__device__ __forceinline__ void acc_edge(uint2 u, float n, float* a1, float* a2) {
    float2 f0 = __half22float2(*reinterpret_cast<__half2*>(&u.x));
    float2 f1 = __half22float2(*reinterpret_cast<__half2*>(&u.y));
    a2[0] += f0.x; a2[1] += f0.y; a2[2] += f1.x; a2[3] += f1.y;
    a1[0] = fmaf(f0.x, n, a1[0]); a1[1] = fmaf(f0.y, n, a1[1]);
    a1[2] = fmaf(f1.x, n, a1[2]); a1[3] = fmaf(f1.y, n, a1[3]);
}

__global__ __launch_bounds__(256) void k_spmm(const uint2* __restrict__ x) {
    int w    = (blockIdx.x * 256 + threadIdx.x) >> 5;
    int lane = threadIdx.x & 31;
    if (w >= NN) return;
    int s = g_rowstart[w];
    int e = g_rowstart[w + 1];
    float a1[4] = {0.f, 0.f, 0.f, 0.f};
    float a2[4] = {0.f, 0.f, 0.f, 0.f};
    int p = s;
    for (; p + 3 < e; p += 4) {
        int   j[4];
        float n[4];
        uint2 u[4];
        #pragma unroll
        for (int q = 0; q < 4; ++q) j[q] = g_csr[p + q];
        #pragma unroll
        for (int q = 0; q < 4; ++q) n[q] = g_ns[j[q]];
        #pragma unroll
        for (int q = 0; q < 4; ++q) u[q] = x[(size_t)j[q] * 32 + lane];
        #pragma unroll
        for (int q = 0; q < 4; ++q) acc_edge(u[q], n[q], a1, a2);
    }
    for (; p < e; ++p) {
        int j0 = g_csr[p];
        float n0 = g_ns[j0];
        uint2 u0 = x[(size_t)j0 * 32 + lane];
        acc_edge(u0, n0, a1, a2);
    }
    float nd = g_nd[w];
    __half2 p0 = __floats2half2_rn(a1[0] * nd, a1[1] * nd);
    __half2 p1 = __floats2half2_rn(a1[2] * nd, a1[3] * nd);
    __half2 p2 = __floats2half2_rn(a2[0], a2[1]);
    __half2 p3 = __floats2half2_rn(a2[2], a2[3]);
    uint2 o1, o2;
    o1.x = *reinterpret_cast<uint32_t*>(&p0);
    o1.y = *reinterpret_cast<uint32_t*>(&p1);
    o2.x = *reinterpret_cast<uint32_t*>(&p2);
    o2.y = *reinterpret_cast<uint32_t*>(&p3);
    uint2* yp = (uint2*)g_yh;
    yp[(size_t)w * 64 + lane]      = o1;
    yp[(size_t)w * 64 + 32 + lane] = o2;
}

// ---------------- GEMM: C[M,BN] = A[M,256] @ Bt[BN,256]^T + bias (fp16 mma) ---
template <int BN, bool RELU, bool HALFOUT>
__global__ __launch_bounds__(256) void k_gemm(
    const uint32_t* __restrict__ A, const uint32_t* __restrict__ Bw,
    const float* __restrict__ bias, void* __restrict__ Cv)
{
    constexpr int BM = 128;
    constexpr int AS = 36;                 // stage row stride in words (64h + pad)
    constexpr int ASTG = BM * AS;
    constexpr int BSTG = BN * AS;
    constexpr int NT = BN / 16;            // n-tiles per warp (warp n-span BN/2)
    constexpr int NKC = 4;                 // 256 / 64 chunks

    extern __shared__ uint32_t dyn[];
    uint32_t* sA = dyn;
    uint32_t* sB = dyn + 2 * ASTG;
    const uint32_t saddrA = (uint32_t)__cvta_generic_to_shared(sA);
    const uint32_t saddrB = (uint32_t)__cvta_generic_to_shared(sB);

    const int tid  = threadIdx.x;
    const int warp = tid >> 5, lane = tid & 31;
    const int grp  = lane >> 2, tig = lane & 3;
    const int wm   = (warp >> 1) * 32;
    const int wn   = (warp & 1) * (BN / 2);
    const int blockRow = blockIdx.x * BM;

    auto stage = [&](int kc, int buf) {
        #pragma unroll
        for (int it = 0; it < 4; ++it) {       // A chunk: 128 rows x 64 halves
            int idx = tid + it * 256;
            int r = idx >> 3, c = idx & 7;
            cp16(saddrA + (uint32_t)(buf * ASTG + r * AS + c * 4) * 4,
                 A + (size_t)(blockRow + r) * 128 + kc * 32 + c * 4);
        }
        #pragma unroll
        for (int it = 0; it < BN / 32; ++it) { // B chunk: BN rows x 64 halves
            int idx = tid + it * 256;
            int r = idx >> 3, c = idx & 7;
            cp16(saddrB + (uint32_t)(buf * BSTG + r * AS + c * 4) * 4,
                 Bw + (size_t)r * 128 + kc * 32 + c * 4);
        }
        cpcommit();
    };

    float acc[2][NT][4];
    #pragma unroll
    for (int mt = 0; mt < 2; mt++)
        #pragma unroll
        for (int nt = 0; nt < NT; nt++)
            #pragma unroll
            for (int r = 0; r < 4; r++) acc[mt][nt][r] = 0.f;

    stage(0, 0);
    #pragma unroll
    for (int kc = 0; kc < NKC; ++kc) {
        int buf = kc & 1;
        if (kc + 1 < NKC) {
            stage(kc + 1, buf ^ 1);
            cpwait<1>();
        } else {
            cpwait<0>();
        }
        __syncthreads();

        const uint32_t* cA = sA + buf * ASTG;
        const uint32_t* cB = sB + buf * BSTG;
        #pragma unroll
        for (int ks = 0; ks < 4; ++ks) {       // 4 x k16 per 64-half chunk
            uint32_t af[2][4];
            #pragma unroll
            for (int mt = 0; mt < 2; mt++) {
                int row = wm + mt * 16 + grp;
                int ko = ks * 8 + tig;
                af[mt][0] = cA[row * AS + ko];
                af[mt][1] = cA[(row + 8) * AS + ko];
                af[mt][2] = cA[row * AS + ko + 4];
                af[mt][3] = cA[(row + 8) * AS + ko + 4];
            }
            uint32_t bf[NT][2];
            #pragma unroll
            for (int nt = 0; nt < NT; nt++) {
                int col = wn + nt * 8 + grp;
                int ko = ks * 8 + tig;
                bf[nt][0] = cB[col * AS + ko];
                bf[nt][1] = cB[col * AS + ko + 4];
            }
            #pragma unroll
            for (int mt = 0; mt < 2; mt++)
                #pragma unroll
                for (int nt = 0; nt < NT; nt++)
                    mma_f16(acc[mt][nt], af[mt], bf[nt]);
        }
        __syncthreads();
    }

    // epilogue: bias (+relu), half2 or float2 stores
    #pragma unroll
    for (int mt = 0; mt < 2; ++mt) {
        int r0 = blockRow + wm + mt * 16 + grp;
        int r1 = r0 + 8;
        #pragma unroll
        for (int nt = 0; nt < NT; ++nt) {
            int col = wn + nt * 8 + 2 * tig;
            float b0v = bias[col], b1v = bias[col + 1];
            float v0 = acc[mt][nt][0] + b0v;
            float v1 = acc[mt][nt][1] + b1v;
            float v2 = acc[mt][nt][2] + b0v;
            float v3 = acc[mt][nt][3] + b1v;
            if (RELU) {
                v0 = fmaxf(v0, 0.f); v1 = fmaxf(v1, 0.f);
                v2 = fmaxf(v2, 0.f); v3 = fmaxf(v3, 0.f);
            }
            if (HALFOUT) {
                __half* C = (__half*)Cv;
                if (r0 < NN)
                    *reinterpret_cast<__half2*>(&C[(size_t)r0 * BN + col]) =
                        __floats2half2_rn(v0, v1);
                if (r1 < NN)
                    *reinterpret_cast<__half2*>(&C[(size_t)r1 * BN + col]) =
                        __floats2half2_rn(v2, v3);
            } else {
                float* C = (float*)Cv;
                if (r0 < NN)
                    *reinterpret_cast<float2*>(&C[(size_t)r0 * BN + col]) = make_float2(v0, v1);
                if (r1 < NN)
                    *reinterpret_cast<float2*>(&C[(size_t)r1 * BN + col]) = make_float2(v2, v3);
            }
        }
    }
}

// ---------------- launcher ----------------------------------------------------
extern "C" void kernel_launch(void* const* d_in, const int* in_sizes, int n_in,
                              void* d_out, int out_size) {
    const float* raw_x = (const float*)d_in[0];
    const int*   src   = (const int*)d_in[1];
    const int*   dst   = (const int*)d_in[2];
    const float* w0    = (const float*)d_in[3];
    const float* b0    = (const float*)d_in[4];
    const float* w1    = (const float*)d_in[5];
    const float* b1    = (const float*)d_in[6];
    const float* w2    = (const float*)d_in[7];
    const float* b2    = (const float*)d_in[8];
    const float* rw0   = (const float*)d_in[9];
    const float* rw1   = (const float*)d_in[10];
    const float* rw2   = (const float*)d_in[11];
    float* out = (float*)d_out;

    void *py = nullptr, *pf0 = nullptr, *pf1 = nullptr;
    void *pw0 = nullptr, *pw1 = nullptr, *pw2 = nullptr;
    cudaGetSymbolAddress(&py, g_yh);
    cudaGetSymbolAddress(&pf0, g_f0);
    cudaGetSymbolAddress(&pf1, g_f1);
    cudaGetSymbolAddress(&pw0, g_wt0);
    cudaGetSymbolAddress(&pw1, g_wt1);
    cudaGetSymbolAddress(&pw2, g_wt2);

    constexpr int SMEM128 = 2 * (128 * 36 + 128 * 36) * 4;  // 73728
    constexpr int SMEM64  = 2 * (128 * 36 + 64 * 36) * 4;   // 55296
    cudaFuncSetAttribute(k_gemm<128, true, true>,
                         cudaFuncAttributeMaxDynamicSharedMemorySize, SMEM128);
    cudaFuncSetAttribute(k_gemm<64, false, false>,
                         cudaFuncAttributeMaxDynamicSharedMemorySize, SMEM64);

    const int TB = 256;
    k_prep<<<(3331920 + TB - 1) / TB, TB>>>((const float4*)raw_x,
                                            w0, rw0, w1, rw1, w2, rw2);
    k_deg<<<(NE / 4 + TB - 1) / TB, TB>>>((const int4*)src, (const int4*)dst);
    k_scan1<<<SCAN_NB, 1024>>>();
    k_scan23<<<(NN + TB - 1) / TB, TB>>>();
    k_csr<<<(NE / 4 + TB - 1) / TB, TB>>>((const int4*)src, (const int4*)dst);

    const int SPMM_BLOCKS = (NN * 32 + TB - 1) / TB;  // one warp per node
    const int GEMM_BLOCKS = NN_PAD / 128;             // 782

    // layer 1: spmm(g_f0=x) -> g_yh ; gemm -> g_f1 (h1, fp16)
    k_spmm<<<SPMM_BLOCKS, TB>>>((const uint2*)pf0);
    k_gemm<128, true, true><<<GEMM_BLOCKS, TB, SMEM128>>>(
        (const uint32_t*)py, (const uint32_t*)pw0, b0, pf1);
    // layer 2: spmm(g_f1) -> g_yh ; gemm -> g_f0 (h2, fp16)
    k_spmm<<<SPMM_BLOCKS, TB>>>((const uint2*)pf1);
    k_gemm<128, true, true><<<GEMM_BLOCKS, TB, SMEM128>>>(
        (const uint32_t*)py, (const uint32_t*)pw1, b1, pf0);
    // layer 3: spmm(g_f0) -> g_yh ; gemm -> d_out (fp32)
    k_spmm<<<SPMM_BLOCKS, TB>>>((const uint2*)pf0);
    k_gemm<64, false, false><<<GEMM_BLOCKS, TB, SMEM64>>>(
        (const uint32_t*)py, (const uint32_t*)pw2, b2, out);
}

// round 14
// speedup vs baseline: 1.8664x; 1.0463x over previous
#include <cuda_runtime.h>
#include <cuda_fp16.h>
#include <cstdint>

#define NN 100000
#define NN_PAD 100096          // 782 * 128
#define NE 1600000
#define SCAN_NB 98             // ceil(NN/1024)

// ---------------- scratch (static __device__ arrays; no allocation) ----------
__device__ __half g_yh[NN_PAD * 256]; // [N,256] fp16: [spmm(x*ns)*nd | spmm(x)]
__device__ uint2  g_f0[NN * 32];      // [N,128] fp16 features buffer A
__device__ uint2  g_f1[NN * 32];      // [N,128] fp16 features buffer B
__device__ int    g_csr[NE];          // src ids grouped by dst
__device__ int    g_rank[NE];         // per-edge rank within its dst bucket
__device__ int    g_outdeg[NN];
__device__ int    g_indeg[NN];
__device__ float  g_ns[NN];
__device__ float  g_nd[NN];
__device__ int    g_rowstart[NN + 1];
__device__ int    g_blocksums[128];
__device__ __half g_wt0[128 * 256];   // [128n][256k] fp16: transposed [w0;rw0]
__device__ __half g_wt1[128 * 256];   // [128n][256k] fp16: transposed [w1;rw1]
__device__ __half g_wt2[64 * 256];    // [64n][256k]  fp16: transposed [w2;rw2]

// ---------------- helpers ----------------------------------------------------
__device__ __forceinline__ void mma_f16(float* c, const uint32_t* a, const uint32_t* b) {
    asm volatile(
        "mma.sync.aligned.m16n8k16.row.col.f32.f16.f16.f32 "
        "{%0,%1,%2,%3}, {%4,%5,%6,%7}, {%8,%9}, {%0,%1,%2,%3};\n"
        : "+f"(c[0]), "+f"(c[1]), "+f"(c[2]), "+f"(c[3])
        : "r"(a[0]), "r"(a[1]), "r"(a[2]), "r"(a[3]), "r"(b[0]), "r"(b[1]));
}

__device__ __forceinline__ void ldsm_x4(uint32_t* r, uint32_t addr) {
    asm volatile(
        "ldmatrix.sync.aligned.m8n8.x4.shared.b16 {%0,%1,%2,%3}, [%4];"
        : "=r"(r[0]), "=r"(r[1]), "=r"(r[2]), "=r"(r[3]) : "r"(addr));
}

__device__ __forceinline__ void cp16(uint32_t dst, const void* src) {
    asm volatile("cp.async.cg.shared.global [%0], [%1], 16;\n" :: "r"(dst), "l"(src));
}
__device__ __forceinline__ void cpcommit() {
    asm volatile("cp.async.commit_group;\n");
}
template <int N>
__device__ __forceinline__ void cpwait() {
    asm volatile("cp.async.wait_group %0;\n" :: "n"(N));
}

// ---------------- fused prep: weights->fp16 transposed, zero degs, x->fp16 ----
__global__ void k_prep(const float4* __restrict__ raw_x,
                       const float* __restrict__ w0, const float* __restrict__ rw0,
                       const float* __restrict__ w1, const float* __restrict__ rw1,
                       const float* __restrict__ w2, const float* __restrict__ rw2) {
    int i = blockIdx.x * blockDim.x + threadIdx.x;
    if (i < 32768) {
        int k = i >> 7, n = i & 127;
        float v = (k < 128) ? w0[k * 128 + n] : rw0[(k - 128) * 128 + n];
        g_wt0[n * 256 + k] = __float2half(v);
    } else if (i < 65536) {
        int j = i - 32768;
        int k = j >> 7, n = j & 127;
        float v = (k < 128) ? w1[k * 128 + n] : rw1[(k - 128) * 128 + n];
        g_wt1[n * 256 + k] = __float2half(v);
    } else if (i < 81920) {
        int j = i - 65536;
        int k = j >> 6, n = j & 63;
        float v = (k < 128) ? w2[k * 64 + n] : rw2[(k - 128) * 64 + n];
        g_wt2[n * 256 + k] = __float2half(v);
    } else if (i < 106920) {
        ((int4*)g_outdeg)[i - 81920] = make_int4(0, 0, 0, 0);
    } else if (i < 131920) {
        ((int4*)g_indeg)[i - 106920] = make_int4(0, 0, 0, 0);
    } else if (i < 3331920) {
        int j = i - 131920;                 // float4 index == uint2 index
        float4 v = raw_x[j];
        __half2 h0 = __floats2half2_rn(v.x, v.y);
        __half2 h1 = __floats2half2_rn(v.z, v.w);
        uint2 u;
        u.x = *reinterpret_cast<uint32_t*>(&h0);
        u.y = *reinterpret_cast<uint32_t*>(&h1);
        g_f0[j] = u;
    }
}

// ---------------- degree count + per-edge dst rank ----------------------------
__global__ void k_deg(const int4* __restrict__ src4, const int4* __restrict__ dst4) {
    int e = blockIdx.x * blockDim.x + threadIdx.x;
    if (e < NE / 4) {
        int4 s = src4[e];
        int4 d = dst4[e];
        atomicAdd(&g_outdeg[s.x], 1); atomicAdd(&g_outdeg[s.y], 1);
        atomicAdd(&g_outdeg[s.z], 1); atomicAdd(&g_outdeg[s.w], 1);
        int4 r;
        r.x = atomicAdd(&g_indeg[d.x], 1);
        r.y = atomicAdd(&g_indeg[d.y], 1);
        r.z = atomicAdd(&g_indeg[d.z], 1);
        r.w = atomicAdd(&g_indeg[d.w], 1);
        ((int4*)g_rank)[e] = r;
    }
}

// exclusive scan of g_indeg (per-block) + blocksums + norms
__global__ void k_scan1() {
    __shared__ int sh[1024];
    int t = threadIdx.x;
    int i = blockIdx.x * 1024 + t;
    int v = (i < NN) ? g_indeg[i] : 0;
    sh[t] = v;
    __syncthreads();
    #pragma unroll
    for (int off = 1; off < 1024; off <<= 1) {
        int add = (t >= off) ? sh[t - off] : 0;
        __syncthreads();
        sh[t] += add;
        __syncthreads();
    }
    if (i < NN) {
        g_rowstart[i] = sh[t] - v;  // exclusive within block
        g_ns[i] = rsqrtf(fmaxf((float)g_outdeg[i], 1.0f));
        g_nd[i] = rsqrtf(fmaxf((float)v, 1.0f));
    }
    if (t == 1023) g_blocksums[blockIdx.x] = sh[1023];
}

// apply block offsets (Hillis-Steele over blocksums)
__global__ void k_scan23() {
    __shared__ int sh[128];
    int t = threadIdx.x;
    int v = (t < SCAN_NB) ? g_blocksums[t] : 0;
    if (t < 128) sh[t] = v;
    __syncthreads();
    #pragma unroll
    for (int off = 1; off < 128; off <<= 1) {
        int add = (t < 128 && t >= off) ? sh[t - off] : 0;
        __syncthreads();
        if (t < 128) sh[t] += add;
        __syncthreads();
    }
    int i = blockIdx.x * blockDim.x + t;
    if (i < NN) {
        int b = i >> 10;
        int pre = (b > 0) ? sh[b - 1] : 0;
        g_rowstart[i] += pre;
    }
    if (i == 0) g_rowstart[NN] = NE;
}

// atomic-free CSR fill: pos = rowstart[dst] + rank
__global__ void k_csr(const int4* __restrict__ src4, const int4* __restrict__ dst4) {
    int e = blockIdx.x * blockDim.x + threadIdx.x;
    if (e < NE / 4) {
        int4 s = src4[e];
        int4 d = dst4[e];
        int4 r = ((const int4*)g_rank)[e];
        g_csr[g_rowstart[d.x] + r.x] = s.x;
        g_csr[g_rowstart[d.y] + r.y] = s.y;
        g_csr[g_rowstart[d.z] + r.z] = s.z;
        g_csr[g_rowstart[d.w] + r.w] = s.w;
    }
}

// ---------------- SpMM: warp per node, unroll 4, fp32 accum -------------------
__device__ __forceinline__ void acc_edge(uint2 u, float n, float* a1, float* a2) {
    float2 f0 = __half22float2(*reinterpret_cast<__half2*>(&u.x));
    float2 f1 = __half22float2(*reinterpret_cast<__half2*>(&u.y));
    a2[0] += f0.x; a2[1] += f0.y; a2[2] += f1.x; a2[3] += f1.y;
    a1[0] = fmaf(f0.x, n, a1[0]); a1[1] = fmaf(f0.y, n, a1[1]);
    a1[2] = fmaf(f1.x, n, a1[2]); a1[3] = fmaf(f1.y, n, a1[3]);
}

__global__ __launch_bounds__(256) void k_spmm(const uint2* __restrict__ x) {
    int w    = (blockIdx.x * 256 + threadIdx.x) >> 5;
    int lane = threadIdx.x & 31;
    if (w >= NN) return;
    int s = g_rowstart[w];
    int e = g_rowstart[w + 1];
    float a1[4] = {0.f, 0.f, 0.f, 0.f};
    float a2[4] = {0.f, 0.f, 0.f, 0.f};
    int p = s;
    for (; p + 3 < e; p += 4) {
        int   j[4];
        float n[4];
        uint2 u[4];
        #pragma unroll
        for (int q = 0; q < 4; ++q) j[q] = g_csr[p + q];
        #pragma unroll
        for (int q = 0; q < 4; ++q) n[q] = g_ns[j[q]];
        #pragma unroll
        for (int q = 0; q < 4; ++q) u[q] = x[(size_t)j[q] * 32 + lane];
        #pragma unroll
        for (int q = 0; q < 4; ++q) acc_edge(u[q], n[q], a1, a2);
    }
    for (; p < e; ++p) {
        int j0 = g_csr[p];
        float n0 = g_ns[j0];
        uint2 u0 = x[(size_t)j0 * 32 + lane];
        acc_edge(u0, n0, a1, a2);
    }
    float nd = g_nd[w];
    __half2 p0 = __floats2half2_rn(a1[0] * nd, a1[1] * nd);
    __half2 p1 = __floats2half2_rn(a1[2] * nd, a1[3] * nd);
    __half2 p2 = __floats2half2_rn(a2[0], a2[1]);
    __half2 p3 = __floats2half2_rn(a2[2], a2[3]);
    uint2 o1, o2;
    o1.x = *reinterpret_cast<uint32_t*>(&p0);
    o1.y = *reinterpret_cast<uint32_t*>(&p1);
    o2.x = *reinterpret_cast<uint32_t*>(&p2);
    o2.y = *reinterpret_cast<uint32_t*>(&p3);
    uint2* yp = (uint2*)g_yh;
    yp[(size_t)w * 64 + lane]      = o1;
    yp[(size_t)w * 64 + 32 + lane] = o2;
}

// ---------------- GEMM: C[M,BN] = A[M,256] @ Bt[BN,256]^T + bias (fp16 mma) ---
// Fragment loads via ldmatrix.m8n8.x4 (6 LDSM/ks vs 24 LDS/ks).
template <int BN, bool RELU, bool HALFOUT>
__global__ __launch_bounds__(256) void k_gemm(
    const uint32_t* __restrict__ A, const uint32_t* __restrict__ Bw,
    const float* __restrict__ bias, void* __restrict__ Cv)
{
    constexpr int BM = 128;
    constexpr int AS = 36;                 // stage row stride in words (64h + pad)
    constexpr int ASTG = BM * AS;
    constexpr int BSTG = BN * AS;
    constexpr int NT = BN / 16;            // n-tiles per warp (warp n-span BN/2)
    constexpr int NKC = 4;                 // 256 / 64 chunks

    extern __shared__ uint32_t dyn[];
    uint32_t* sA = dyn;
    uint32_t* sB = dyn + 2 * ASTG;
    const uint32_t saddrA = (uint32_t)__cvta_generic_to_shared(sA);
    const uint32_t saddrB = (uint32_t)__cvta_generic_to_shared(sB);

    const int tid  = threadIdx.x;
    const int warp = tid >> 5, lane = tid & 31;
    const int grp  = lane >> 2, tig = lane & 3;
    const int wm   = (warp >> 1) * 32;
    const int wn   = (warp & 1) * (BN / 2);
    const int blockRow = blockIdx.x * BM;

    // ldmatrix lane addressing
    const int lrowA = lane & 15;           // row within 16-row group
    const int kwA   = (lane >> 4) * 4;     // k-half select (words)
    const int subB  = lane & 7;            // n within 8
    const int nselB = (lane & 16) ? 8 : 0; // second n-octet
    const int kwB   = (lane & 8) ? 4 : 0;  // k-half select (words)

    auto stage = [&](int kc, int buf) {
        #pragma unroll
        for (int it = 0; it < 4; ++it) {       // A chunk: 128 rows x 64 halves
            int idx = tid + it * 256;
            int r = idx >> 3, c = idx & 7;
            cp16(saddrA + (uint32_t)(buf * ASTG + r * AS + c * 4) * 4,
                 A + (size_t)(blockRow + r) * 128 + kc * 32 + c * 4);
        }
        #pragma unroll
        for (int it = 0; it < BN / 32; ++it) { // B chunk: BN rows x 64 halves
            int idx = tid + it * 256;
            int r = idx >> 3, c = idx & 7;
            cp16(saddrB + (uint32_t)(buf * BSTG + r * AS + c * 4) * 4,
                 Bw + (size_t)r * 128 + kc * 32 + c * 4);
        }
        cpcommit();
    };

    float acc[2][NT][4];
    #pragma unroll
    for (int mt = 0; mt < 2; mt++)
        #pragma unroll
        for (int nt = 0; nt < NT; nt++)
            #pragma unroll
            for (int r = 0; r < 4; r++) acc[mt][nt][r] = 0.f;

    stage(0, 0);
    #pragma unroll
    for (int kc = 0; kc < NKC; ++kc) {
        int buf = kc & 1;
        if (kc + 1 < NKC) {
            stage(kc + 1, buf ^ 1);
            cpwait<1>();
        } else {
            cpwait<0>();
        }
        __syncthreads();

        const uint32_t baseA = saddrA + (uint32_t)(buf * ASTG) * 4;
        const uint32_t baseB = saddrB + (uint32_t)(buf * BSTG) * 4;
        #pragma unroll
        for (int ks = 0; ks < 4; ++ks) {       // 4 x k16 per 64-half chunk
            uint32_t af[2][4];
            #pragma unroll
            for (int mt = 0; mt < 2; mt++) {
                uint32_t addr = baseA +
                    (uint32_t)((wm + mt * 16 + lrowA) * AS + ks * 8 + kwA) * 4;
                ldsm_x4(af[mt], addr);
            }
            uint32_t bf[NT][2];
            #pragma unroll
            for (int np = 0; np < NT / 2; np++) {
                uint32_t tmp[4];
                uint32_t addr = baseB +
                    (uint32_t)((wn + np * 16 + subB + nselB) * AS + ks * 8 + kwB) * 4;
                ldsm_x4(tmp, addr);
                bf[2 * np][0]     = tmp[0];
                bf[2 * np][1]     = tmp[1];
                bf[2 * np + 1][0] = tmp[2];
                bf[2 * np + 1][1] = tmp[3];
            }
            #pragma unroll
            for (int mt = 0; mt < 2; mt++)
                #pragma unroll
                for (int nt = 0; nt < NT; nt++)
                    mma_f16(acc[mt][nt], af[mt], bf[nt]);
        }
        __syncthreads();
    }

    // epilogue: bias (+relu), half2 or float2 stores
    #pragma unroll
    for (int mt = 0; mt < 2; ++mt) {
        int r0 = blockRow + wm + mt * 16 + grp;
        int r1 = r0 + 8;
        #pragma unroll
        for (int nt = 0; nt < NT; ++nt) {
            int col = wn + nt * 8 + 2 * tig;
            float b0v = bias[col], b1v = bias[col + 1];
            float v0 = acc[mt][nt][0] + b0v;
            float v1 = acc[mt][nt][1] + b1v;
            float v2 = acc[mt][nt][2] + b0v;
            float v3 = acc[mt][nt][3] + b1v;
            if (RELU) {
                v0 = fmaxf(v0, 0.f); v1 = fmaxf(v1, 0.f);
                v2 = fmaxf(v2, 0.f); v3 = fmaxf(v3, 0.f);
            }
            if (HALFOUT) {
                __half* C = (__half*)Cv;
                if (r0 < NN)
                    *reinterpret_cast<__half2*>(&C[(size_t)r0 * BN + col]) =
                        __floats2half2_rn(v0, v1);
                if (r1 < NN)
                    *reinterpret_cast<__half2*>(&C[(size_t)r1 * BN + col]) =
                        __floats2half2_rn(v2, v3);
            } else {
                float* C = (float*)Cv;
                if (r0 < NN)
                    *reinterpret_cast<float2*>(&C[(size_t)r0 * BN + col]) = make_float2(v0, v1);
                if (r1 < NN)
                    *reinterpret_cast<float2*>(&C[(size_t)r1 * BN + col]) = make_float2(v2, v3);
            }
        }
    }
}

// ---------------- launcher ----------------------------------------------------
extern "C" void kernel_launch(void* const* d_in, const int* in_sizes, int n_in,
                              void* d_out, int out_size) {
    const float* raw_x = (const float*)d_in[0];
    const int*   src   = (const int*)d_in[1];
    const int*   dst   = (const int*)d_in[2];
    const float* w0    = (const float*)d_in[3];
    const float* b0    = (const float*)d_in[4];
    const float* w1    = (const float*)d_in[5];
    const float* b1    = (const float*)d_in[6];
    const float* w2    = (const float*)d_in[7];
    const float* b2    = (const float*)d_in[8];
    const float* rw0   = (const float*)d_in[9];
    const float* rw1   = (const float*)d_in[10];
    const float* rw2   = (const float*)d_in[11];
    float* out = (float*)d_out;

    void *py = nullptr, *pf0 = nullptr, *pf1 = nullptr;
    void *pw0 = nullptr, *pw1 = nullptr, *pw2 = nullptr;
    cudaGetSymbolAddress(&py, g_yh);
    cudaGetSymbolAddress(&pf0, g_f0);
    cudaGetSymbolAddress(&pf1, g_f1);
    cudaGetSymbolAddress(&pw0, g_wt0);
    cudaGetSymbolAddress(&pw1, g_wt1);
    cudaGetSymbolAddress(&pw2, g_wt2);

    constexpr int SMEM128 = 2 * (128 * 36 + 128 * 36) * 4;  // 73728
    constexpr int SMEM64  = 2 * (128 * 36 + 64 * 36) * 4;   // 55296
    cudaFuncSetAttribute(k_gemm<128, true, true>,
                         cudaFuncAttributeMaxDynamicSharedMemorySize, SMEM128);
    cudaFuncSetAttribute(k_gemm<64, false, false>,
                         cudaFuncAttributeMaxDynamicSharedMemorySize, SMEM64);

    const int TB = 256;
    k_prep<<<(3331920 + TB - 1) / TB, TB>>>((const float4*)raw_x,
                                            w0, rw0, w1, rw1, w2, rw2);
    k_deg<<<(NE / 4 + TB - 1) / TB, TB>>>((const int4*)src, (const int4*)dst);
    k_scan1<<<SCAN_NB, 1024>>>();
    k_scan23<<<(NN + TB - 1) / TB, TB>>>();
    k_csr<<<(NE / 4 + TB - 1) / TB, TB>>>((const int4*)src, (const int4*)dst);

    const int SPMM_BLOCKS = (NN * 32 + TB - 1) / TB;  // one warp per node
    const int GEMM_BLOCKS = NN_PAD / 128;             // 782

    // layer 1: spmm(g_f0=x) -> g_yh ; gemm -> g_f1 (h1, fp16)
    k_spmm<<<SPMM_BLOCKS, TB>>>((const uint2*)pf0);
    k_gemm<128, true, true><<<GEMM_BLOCKS, TB, SMEM128>>>(
        (const uint32_t*)py, (const uint32_t*)pw0, b0, pf1);
    // layer 2: spmm(g_f1) -> g_yh ; gemm -> g_f0 (h2, fp16)
    k_spmm<<<SPMM_BLOCKS, TB>>>((const uint2*)pf1);
    k_gemm<128, true, true><<<GEMM_BLOCKS, TB, SMEM128>>>(
        (const uint32_t*)py, (const uint32_t*)pw1, b1, pf0);
    // layer 3: spmm(g_f0) -> g_yh ; gemm -> d_out (fp32)
    k_spmm<<<SPMM_BLOCKS, TB>>>((const uint2*)pf0);
    k_gemm<64, false, false><<<GEMM_BLOCKS, TB, SMEM64>>>(
        (const uint32_t*)py, (const uint32_t*)pw2, b2, out);
}

// round 16
// speedup vs baseline: 1.9462x; 1.0427x over previous
#include <cuda_runtime.h>
#include <cuda_fp16.h>
#include <cstdint>

#define NN 100000
#define NN_PAD 100096          // 782 * 128
#define NE 1600000
#define SCAN_NB 98             // ceil(NN/1024)

// ---------------- scratch (static __device__ arrays; no allocation) ----------
__device__ __half g_yh[NN_PAD * 256]; // [N,256] fp16: [spmm(x*ns)*nd | spmm(x)]
__device__ uint2  g_f0[NN * 32];      // [N,128] fp16 features buffer A
__device__ uint2  g_f1[NN * 32];      // [N,128] fp16 features buffer B
__device__ int2   g_csr2[NE];         // {src id, ns_bits} grouped by dst
__device__ int    g_rank[NE];         // per-edge rank within its dst bucket
__device__ int    g_outdeg[NN];
__device__ int    g_indeg[NN];
__device__ float  g_ns[NN];
__device__ float  g_nd[NN];
__device__ int    g_rowstart[NN + 1];
__device__ int    g_blocksums[128];
__device__ __half g_wt0[128 * 256];   // [128n][256k] fp16: transposed [w0;rw0]
__device__ __half g_wt1[128 * 256];   // [128n][256k] fp16: transposed [w1;rw1]
__device__ __half g_wt2[64 * 256];    // [64n][256k]  fp16: transposed [w2;rw2]

// ---------------- helpers ----------------------------------------------------
__device__ __forceinline__ void mma_f16(float* c, const uint32_t* a, const uint32_t* b) {
    asm volatile(
        "mma.sync.aligned.m16n8k16.row.col.f32.f16.f16.f32 "
        "{%0,%1,%2,%3}, {%4,%5,%6,%7}, {%8,%9}, {%0,%1,%2,%3};\n"
        : "+f"(c[0]), "+f"(c[1]), "+f"(c[2]), "+f"(c[3])
        : "r"(a[0]), "r"(a[1]), "r"(a[2]), "r"(a[3]), "r"(b[0]), "r"(b[1]));
}

__device__ __forceinline__ void ldsm_x4(uint32_t* r, uint32_t addr) {
    asm volatile(
        "ldmatrix.sync.aligned.m8n8.x4.shared.b16 {%0,%1,%2,%3}, [%4];"
        : "=r"(r[0]), "=r"(r[1]), "=r"(r[2]), "=r"(r[3]) : "r"(addr));
}

__device__ __forceinline__ void cp16(uint32_t dst, const void* src) {
    asm volatile("cp.async.cg.shared.global [%0], [%1], 16;\n" :: "r"(dst), "l"(src));
}
__device__ __forceinline__ void cpcommit() {
    asm volatile("cp.async.commit_group;\n");
}
template <int N>
__device__ __forceinline__ void cpwait() {
    asm volatile("cp.async.wait_group %0;\n" :: "n"(N));
}

// ---------------- fused prep: weights->fp16 transposed, zero degs, x->fp16 ----
__global__ void k_prep(const float4* __restrict__ raw_x,
                       const float* __restrict__ w0, const float* __restrict__ rw0,
                       const float* __restrict__ w1, const float* __restrict__ rw1,
                       const float* __restrict__ w2, const float* __restrict__ rw2) {
    int i = blockIdx.x * blockDim.x + threadIdx.x;
    if (i < 32768) {
        int k = i >> 7, n = i & 127;
        float v = (k < 128) ? w0[k * 128 + n] : rw0[(k - 128) * 128 + n];
        g_wt0[n * 256 + k] = __float2half(v);
    } else if (i < 65536) {
        int j = i - 32768;
        int k = j >> 7, n = j & 127;
        float v = (k < 128) ? w1[k * 128 + n] : rw1[(k - 128) * 128 + n];
        g_wt1[n * 256 + k] = __float2half(v);
    } else if (i < 81920) {
        int j = i - 65536;
        int k = j >> 6, n = j & 63;
        float v = (k < 128) ? w2[k * 64 + n] : rw2[(k - 128) * 64 + n];
        g_wt2[n * 256 + k] = __float2half(v);
    } else if (i < 106920) {
        ((int4*)g_outdeg)[i - 81920] = make_int4(0, 0, 0, 0);
    } else if (i < 131920) {
        ((int4*)g_indeg)[i - 106920] = make_int4(0, 0, 0, 0);
    } else if (i < 3331920) {
        int j = i - 131920;                 // float4 index == uint2 index
        float4 v = raw_x[j];
        __half2 h0 = __floats2half2_rn(v.x, v.y);
        __half2 h1 = __floats2half2_rn(v.z, v.w);
        uint2 u;
        u.x = *reinterpret_cast<uint32_t*>(&h0);
        u.y = *reinterpret_cast<uint32_t*>(&h1);
        g_f0[j] = u;
    }
}

// ---------------- degree count + per-edge dst rank ----------------------------
__global__ void k_deg(const int4* __restrict__ src4, const int4* __restrict__ dst4) {
    int e = blockIdx.x * blockDim.x + threadIdx.x;
    if (e < NE / 4) {
        int4 s = src4[e];
        int4 d = dst4[e];
        atomicAdd(&g_outdeg[s.x], 1); atomicAdd(&g_outdeg[s.y], 1);
        atomicAdd(&g_outdeg[s.z], 1); atomicAdd(&g_outdeg[s.w], 1);
        int4 r;
        r.x = atomicAdd(&g_indeg[d.x], 1);
        r.y = atomicAdd(&g_indeg[d.y], 1);
        r.z = atomicAdd(&g_indeg[d.z], 1);
        r.w = atomicAdd(&g_indeg[d.w], 1);
        ((int4*)g_rank)[e] = r;
    }
}

// exclusive scan of g_indeg (per-block) + blocksums + norms
__global__ void k_scan1() {
    __shared__ int sh[1024];
    int t = threadIdx.x;
    int i = blockIdx.x * 1024 + t;
    int v = (i < NN) ? g_indeg[i] : 0;
    sh[t] = v;
    __syncthreads();
    #pragma unroll
    for (int off = 1; off < 1024; off <<= 1) {
        int add = (t >= off) ? sh[t - off] : 0;
        __syncthreads();
        sh[t] += add;
        __syncthreads();
    }
    if (i < NN) {
        g_rowstart[i] = sh[t] - v;  // exclusive within block
        g_ns[i] = rsqrtf(fmaxf((float)g_outdeg[i], 1.0f));
        g_nd[i] = rsqrtf(fmaxf((float)v, 1.0f));
    }
    if (t == 1023) g_blocksums[blockIdx.x] = sh[1023];
}

// apply block offsets (Hillis-Steele over blocksums)
__global__ void k_scan23() {
    __shared__ int sh[128];
    int t = threadIdx.x;
    int v = (t < SCAN_NB) ? g_blocksums[t] : 0;
    if (t < 128) sh[t] = v;
    __syncthreads();
    #pragma unroll
    for (int off = 1; off < 128; off <<= 1) {
        int add = (t < 128 && t >= off) ? sh[t - off] : 0;
        __syncthreads();
        if (t < 128) sh[t] += add;
        __syncthreads();
    }
    int i = blockIdx.x * blockDim.x + t;
    if (i < NN) {
        int b = i >> 10;
        int pre = (b > 0) ? sh[b - 1] : 0;
        g_rowstart[i] += pre;
    }
    if (i == 0) g_rowstart[NN] = NE;
}

// atomic-free CSR fill: pos = rowstart[dst] + rank; payload = {src, ns[src]}
__global__ void k_csr(const int4* __restrict__ src4, const int4* __restrict__ dst4) {
    int e = blockIdx.x * blockDim.x + threadIdx.x;
    if (e < NE / 4) {
        int4 s = src4[e];
        int4 d = dst4[e];
        int4 r = ((const int4*)g_rank)[e];
        int2 v;
        v.x = s.x; v.y = __float_as_int(g_ns[s.x]);
        g_csr2[g_rowstart[d.x] + r.x] = v;
        v.x = s.y; v.y = __float_as_int(g_ns[s.y]);
        g_csr2[g_rowstart[d.y] + r.y] = v;
        v.x = s.z; v.y = __float_as_int(g_ns[s.z]);
        g_csr2[g_rowstart[d.z] + r.z] = v;
        v.x = s.w; v.y = __float_as_int(g_ns[s.w]);
        g_csr2[g_rowstart[d.w] + r.w] = v;
    }
}

// ---------------- SpMM: warp per node, packed CSR (id+ns), unroll 4 -----------
// 2-level dependency chain per edge: csr2 -> x (ns rides with the index).
__device__ __forceinline__ void acc_edge(uint2 u, float n, float* a1, float* a2) {
    float2 f0 = __half22float2(*reinterpret_cast<__half2*>(&u.x));
    float2 f1 = __half22float2(*reinterpret_cast<__half2*>(&u.y));
    a2[0] += f0.x; a2[1] += f0.y; a2[2] += f1.x; a2[3] += f1.y;
    a1[0] = fmaf(f0.x, n, a1[0]); a1[1] = fmaf(f0.y, n, a1[1]);
    a1[2] = fmaf(f1.x, n, a1[2]); a1[3] = fmaf(f1.y, n, a1[3]);
}

__global__ __launch_bounds__(256) void k_spmm(const uint2* __restrict__ x) {
    int w    = (blockIdx.x * 256 + threadIdx.x) >> 5;
    int lane = threadIdx.x & 31;
    if (w >= NN) return;
    int s = g_rowstart[w];
    int e = g_rowstart[w + 1];
    float a1[4] = {0.f, 0.f, 0.f, 0.f};
    float a2[4] = {0.f, 0.f, 0.f, 0.f};
    int p = s;
    for (; p + 3 < e; p += 4) {
        int2  c[4];
        uint2 u[4];
        #pragma unroll
        for (int q = 0; q < 4; ++q) c[q] = g_csr2[p + q];
        #pragma unroll
        for (int q = 0; q < 4; ++q) u[q] = x[(size_t)c[q].x * 32 + lane];
        #pragma unroll
        for (int q = 0; q < 4; ++q) acc_edge(u[q], __int_as_float(c[q].y), a1, a2);
    }
    for (; p < e; ++p) {
        int2 c0 = g_csr2[p];
        uint2 u0 = x[(size_t)c0.x * 32 + lane];
        acc_edge(u0, __int_as_float(c0.y), a1, a2);
    }
    float nd = g_nd[w];
    __half2 p0 = __floats2half2_rn(a1[0] * nd, a1[1] * nd);
    __half2 p1 = __floats2half2_rn(a1[2] * nd, a1[3] * nd);
    __half2 p2 = __floats2half2_rn(a2[0], a2[1]);
    __half2 p3 = __floats2half2_rn(a2[2], a2[3]);
    uint2 o1, o2;
    o1.x = *reinterpret_cast<uint32_t*>(&p0);
    o1.y = *reinterpret_cast<uint32_t*>(&p1);
    o2.x = *reinterpret_cast<uint32_t*>(&p2);
    o2.y = *reinterpret_cast<uint32_t*>(&p3);
    uint2* yp = (uint2*)g_yh;
    yp[(size_t)w * 64 + lane]      = o1;
    yp[(size_t)w * 64 + 32 + lane] = o2;
}

// ---------------- GEMM: C[M,BN] = A[M,256] @ Bt[BN,256]^T + bias (fp16 mma) ---
// Fragment loads via ldmatrix.m8n8.x4 (6 LDSM/ks vs 24 LDS/ks).
template <int BN, bool RELU, bool HALFOUT>
__global__ __launch_bounds__(256) void k_gemm(
    const uint32_t* __restrict__ A, const uint32_t* __restrict__ Bw,
    const float* __restrict__ bias, void* __restrict__ Cv)
{
    constexpr int BM = 128;
    constexpr int AS = 36;                 // stage row stride in words (64h + pad)
    constexpr int ASTG = BM * AS;
    constexpr int BSTG = BN * AS;
    constexpr int NT = BN / 16;            // n-tiles per warp (warp n-span BN/2)
    constexpr int NKC = 4;                 // 256 / 64 chunks

    extern __shared__ uint32_t dyn[];
    uint32_t* sA = dyn;
    uint32_t* sB = dyn + 2 * ASTG;
    const uint32_t saddrA = (uint32_t)__cvta_generic_to_shared(sA);
    const uint32_t saddrB = (uint32_t)__cvta_generic_to_shared(sB);

    const int tid  = threadIdx.x;
    const int warp = tid >> 5, lane = tid & 31;
    const int grp  = lane >> 2, tig = lane & 3;
    const int wm   = (warp >> 1) * 32;
    const int wn   = (warp & 1) * (BN / 2);
    const int blockRow = blockIdx.x * BM;

    // ldmatrix lane addressing
    const int lrowA = lane & 15;           // row within 16-row group
    const int kwA   = (lane >> 4) * 4;     // k-half select (words)
    const int subB  = lane & 7;            // n within 8
    const int nselB = (lane & 16) ? 8 : 0; // second n-octet
    const int kwB   = (lane & 8) ? 4 : 0;  // k-half select (words)

    auto stage = [&](int kc, int buf) {
        #pragma unroll
        for (int it = 0; it < 4; ++it) {       // A chunk: 128 rows x 64 halves
            int idx = tid + it * 256;
            int r = idx >> 3, c = idx & 7;
            cp16(saddrA + (uint32_t)(buf * ASTG + r * AS + c * 4) * 4,
                 A + (size_t)(blockRow + r) * 128 + kc * 32 + c * 4);
        }
        #pragma unroll
        for (int it = 0; it < BN / 32; ++it) { // B chunk: BN rows x 64 halves
            int idx = tid + it * 256;
            int r = idx >> 3, c = idx & 7;
            cp16(saddrB + (uint32_t)(buf * BSTG + r * AS + c * 4) * 4,
                 Bw + (size_t)r * 128 + kc * 32 + c * 4);
        }
        cpcommit();
    };

    float acc[2][NT][4];
    #pragma unroll
    for (int mt = 0; mt < 2; mt++)
        #pragma unroll
        for (int nt = 0; nt < NT; nt++)
            #pragma unroll
            for (int r = 0; r < 4; r++) acc[mt][nt][r] = 0.f;

    stage(0, 0);
    #pragma unroll
    for (int kc = 0; kc < NKC; ++kc) {
        int buf = kc & 1;
        if (kc + 1 < NKC) {
            stage(kc + 1, buf ^ 1);
            cpwait<1>();
        } else {
            cpwait<0>();
        }
        __syncthreads();

        const uint32_t baseA = saddrA + (uint32_t)(buf * ASTG) * 4;
        const uint32_t baseB = saddrB + (uint32_t)(buf * BSTG) * 4;
        #pragma unroll
        for (int ks = 0; ks < 4; ++ks) {       // 4 x k16 per 64-half chunk
            uint32_t af[2][4];
            #pragma unroll
            for (int mt = 0; mt < 2; mt++) {
                uint32_t addr = baseA +
                    (uint32_t)((wm + mt * 16 + lrowA) * AS + ks * 8 + kwA) * 4;
                ldsm_x4(af[mt], addr);
            }
            uint32_t bf[NT][2];
            #pragma unroll
            for (int np = 0; np < NT / 2; np++) {
                uint32_t tmp[4];
                uint32_t addr = baseB +
                    (uint32_t)((wn + np * 16 + subB + nselB) * AS + ks * 8 + kwB) * 4;
                ldsm_x4(tmp, addr);
                bf[2 * np][0]     = tmp[0];
                bf[2 * np][1]     = tmp[1];
                bf[2 * np + 1][0] = tmp[2];
                bf[2 * np + 1][1] = tmp[3];
            }
            #pragma unroll
            for (int mt = 0; mt < 2; mt++)
                #pragma unroll
                for (int nt = 0; nt < NT; nt++)
                    mma_f16(acc[mt][nt], af[mt], bf[nt]);
        }
        __syncthreads();
    }

    // epilogue: bias (+relu), half2 or float2 stores
    #pragma unroll
    for (int mt = 0; mt < 2; ++mt) {
        int r0 = blockRow + wm + mt * 16 + grp;
        int r1 = r0 + 8;
        #pragma unroll
        for (int nt = 0; nt < NT; ++nt) {
            int col = wn + nt * 8 + 2 * tig;
            float b0v = bias[col], b1v = bias[col + 1];
            float v0 = acc[mt][nt][0] + b0v;
            float v1 = acc[mt][nt][1] + b1v;
            float v2 = acc[mt][nt][2] + b0v;
            float v3 = acc[mt][nt][3] + b1v;
            if (RELU) {
                v0 = fmaxf(v0, 0.f); v1 = fmaxf(v1, 0.f);
                v2 = fmaxf(v2, 0.f); v3 = fmaxf(v3, 0.f);
            }
            if (HALFOUT) {
                __half* C = (__half*)Cv;
                if (r0 < NN)
                    *reinterpret_cast<__half2*>(&C[(size_t)r0 * BN + col]) =
                        __floats2half2_rn(v0, v1);
                if (r1 < NN)
                    *reinterpret_cast<__half2*>(&C[(size_t)r1 * BN + col]) =
                        __floats2half2_rn(v2, v3);
            } else {
                float* C = (float*)Cv;
                if (r0 < NN)
                    *reinterpret_cast<float2*>(&C[(size_t)r0 * BN + col]) = make_float2(v0, v1);
                if (r1 < NN)
                    *reinterpret_cast<float2*>(&C[(size_t)r1 * BN + col]) = make_float2(v2, v3);
            }
        }
    }
}

// ---------------- launcher ----------------------------------------------------
extern "C" void kernel_launch(void* const* d_in, const int* in_sizes, int n_in,
                              void* d_out, int out_size) {
    const float* raw_x = (const float*)d_in[0];
    const int*   src   = (const int*)d_in[1];
    const int*   dst   = (const int*)d_in[2];
    const float* w0    = (const float*)d_in[3];
    const float* b0    = (const float*)d_in[4];
    const float* w1    = (const float*)d_in[5];
    const float* b1    = (const float*)d_in[6];
    const float* w2    = (const float*)d_in[7];
    const float* b2    = (const float*)d_in[8];
    const float* rw0   = (const float*)d_in[9];
    const float* rw1   = (const float*)d_in[10];
    const float* rw2   = (const float*)d_in[11];
    float* out = (float*)d_out;

    void *py = nullptr, *pf0 = nullptr, *pf1 = nullptr;
    void *pw0 = nullptr, *pw1 = nullptr, *pw2 = nullptr;
    cudaGetSymbolAddress(&py, g_yh);
    cudaGetSymbolAddress(&pf0, g_f0);
    cudaGetSymbolAddress(&pf1, g_f1);
    cudaGetSymbolAddress(&pw0, g_wt0);
    cudaGetSymbolAddress(&pw1, g_wt1);
    cudaGetSymbolAddress(&pw2, g_wt2);

    constexpr int SMEM128 = 2 * (128 * 36 + 128 * 36) * 4;  // 73728
    constexpr int SMEM64  = 2 * (128 * 36 + 64 * 36) * 4;   // 55296
    cudaFuncSetAttribute(k_gemm<128, true, true>,
                         cudaFuncAttributeMaxDynamicSharedMemorySize, SMEM128);
    cudaFuncSetAttribute(k_gemm<64, false, false>,
                         cudaFuncAttributeMaxDynamicSharedMemorySize, SMEM64);

    const int TB = 256;
    k_prep<<<(3331920 + TB - 1) / TB, TB>>>((const float4*)raw_x,
                                            w0, rw0, w1, rw1, w2, rw2);
    k_deg<<<(NE / 4 + TB - 1) / TB, TB>>>((const int4*)src, (const int4*)dst);
    k_scan1<<<SCAN_NB, 1024>>>();
    k_scan23<<<(NN + TB - 1) / TB, TB>>>();
    k_csr<<<(NE / 4 + TB - 1) / TB, TB>>>((const int4*)src, (const int4*)dst);

    const int SPMM_BLOCKS = (NN * 32 + TB - 1) / TB;  // one warp per node
    const int GEMM_BLOCKS = NN_PAD / 128;             // 782

    // layer 1: spmm(g_f0=x) -> g_yh ; gemm -> g_f1 (h1, fp16)
    k_spmm<<<SPMM_BLOCKS, TB>>>((const uint2*)pf0);
    k_gemm<128, true, true><<<GEMM_BLOCKS, TB, SMEM128>>>(
        (const uint32_t*)py, (const uint32_t*)pw0, b0, pf1);
    // layer 2: spmm(g_f1) -> g_yh ; gemm -> g_f0 (h2, fp16)
    k_spmm<<<SPMM_BLOCKS, TB>>>((const uint2*)pf1);
    k_gemm<128, true, true><<<GEMM_BLOCKS, TB, SMEM128>>>(
        (const uint32_t*)py, (const uint32_t*)pw1, b1, pf0);
    // layer 3: spmm(g_f0) -> g_yh ; gemm -> d_out (fp32)
    k_spmm<<<SPMM_BLOCKS, TB>>>((const uint2*)pf0);
    k_gemm<64, false, false><<<GEMM_BLOCKS, TB, SMEM64>>>(
        (const uint32_t*)py, (const uint32_t*)pw2, b2, out);
}